// round 3
// baseline (speedup 1.0000x reference)
#include <cuda_runtime.h>
#include <math.h>

#define BATCH 8
#define LEN   1024
#define DIN   512
#define NHEAD 8
#define HDIM  64
#define HD    512   // NHEAD*HDIM

// Scratch: q,k,v in [B,H,L,64] layout (device globals; no allocation allowed)
__device__ float g_q[BATCH*NHEAD*LEN*HDIM];
__device__ float g_k[BATCH*NHEAD*LEN*HDIM];
__device__ float g_v[BATCH*NHEAD*LEN*HDIM];

// ---------------------------------------------------------------------------
// Projection GEMM: out[b,h,l,d] = sum_k X[b*L+l][k] * W[k][h*64+d]
// BM=128, BN=128, BK=16, 256 threads, 8x8 microtile, reg-prefetch double buffer
// ---------------------------------------------------------------------------
__global__ __launch_bounds__(256) void proj_kernel(
    const float* __restrict__ X,     // [8192][512]
    const float* __restrict__ W,     // [512][512]
    float* __restrict__ outBHLD)     // [B,H,L,64]
{
    __shared__ float As[16][128];    // [k][m]
    __shared__ float Bs[16][132];    // [k][n] (pad 132)

    const int tid = threadIdx.x;
    const int tx  = tid & 15;        // n-dim thread coord
    const int ty  = tid >> 4;        // m-dim thread coord
    const int m0  = blockIdx.y * 128;
    const int n0  = blockIdx.x * 128;

    // A loader: thread -> row=tid/2, k-offset=(tid&1)*8, two float4s
    const int a_row = tid >> 1;
    const int a_k0  = (tid & 1) * 8;
    // B loader: thread -> k=tid/32 (and +8), n=(tid&31)*4
    const int b_k = tid >> 5;
    const int b_n = (tid & 31) * 4;

    const float* Ag = X + (m0 + a_row) * DIN + a_k0;
    const float* Bg = W + b_k * HD + n0 + b_n;

    float4 pa0 = *(const float4*)(Ag);
    float4 pa1 = *(const float4*)(Ag + 4);
    float4 pb0 = *(const float4*)(Bg);
    float4 pb1 = *(const float4*)(Bg + 8*HD);

    float acc[8][8];
    #pragma unroll
    for (int i = 0; i < 8; ++i)
        #pragma unroll
        for (int j = 0; j < 8; ++j) acc[i][j] = 0.0f;

    const int NKT = DIN / 16;  // 32
    for (int kt = 0; kt < NKT; ++kt) {
        // commit prefetched tile to smem (A transposed)
        As[a_k0+0][a_row] = pa0.x; As[a_k0+1][a_row] = pa0.y;
        As[a_k0+2][a_row] = pa0.z; As[a_k0+3][a_row] = pa0.w;
        As[a_k0+4][a_row] = pa1.x; As[a_k0+5][a_row] = pa1.y;
        As[a_k0+6][a_row] = pa1.z; As[a_k0+7][a_row] = pa1.w;
        *(float4*)&Bs[b_k][b_n]     = pb0;
        *(float4*)&Bs[b_k+8][b_n]   = pb1;
        __syncthreads();

        if (kt + 1 < NKT) {
            const float* Ag2 = Ag + (kt+1)*16;
            const float* Bg2 = Bg + (kt+1)*16*HD;
            pa0 = *(const float4*)(Ag2);
            pa1 = *(const float4*)(Ag2 + 4);
            pb0 = *(const float4*)(Bg2);
            pb1 = *(const float4*)(Bg2 + 8*HD);
        }

        #pragma unroll 8
        for (int k = 0; k < 16; ++k) {
            float4 a0 = *(const float4*)&As[k][ty*8];
            float4 a1 = *(const float4*)&As[k][ty*8+4];
            float4 b0 = *(const float4*)&Bs[k][tx*8];
            float4 b1 = *(const float4*)&Bs[k][tx*8+4];
            float av[8] = {a0.x,a0.y,a0.z,a0.w,a1.x,a1.y,a1.z,a1.w};
            float bv[8] = {b0.x,b0.y,b0.z,b0.w,b1.x,b1.y,b1.z,b1.w};
            #pragma unroll
            for (int i = 0; i < 8; ++i)
                #pragma unroll
                for (int j = 0; j < 8; ++j)
                    acc[i][j] = fmaf(av[i], bv[j], acc[i][j]);
        }
        __syncthreads();
    }

    // store to [B,H,L,64]; n0+tx*8 is 8-aligned so each float4 stays in one head
    const int h  = (n0 + tx*8) >> 6;
    const int d0 = (n0 + tx*8) & 63;
    #pragma unroll
    for (int i = 0; i < 8; ++i) {
        const int m = m0 + ty*8 + i;
        const int b = m >> 10;
        const int l = m & 1023;
        float* orow = outBHLD + (((b*NHEAD + h)*LEN + l) * HDIM) + d0;
        *(float4*)(orow)     = make_float4(acc[i][0],acc[i][1],acc[i][2],acc[i][3]);
        *(float4*)(orow + 4) = make_float4(acc[i][4],acc[i][5],acc[i][6],acc[i][7]);
    }
}

// ---------------------------------------------------------------------------
// Causal flash attention, fp32.
// Block: 128 threads, BM=128 queries, BN=64 keys/iter, D=64.
// Thread grid 16(m) x 8(n/d), 8x8 microtiles for S and O.
// ---------------------------------------------------------------------------
__global__ __launch_bounds__(128) void attn_kernel(float* __restrict__ out)
{
    extern __shared__ float sm[];
    float* Qs = sm;                 // [64][128]  (d-major)  32KB
    float* Ks = Qs + 64*128;        // [64][64]   (d-major)  16KB
    float* Vs = Ks + 64*64;         // [64][64]   (n-major)  16KB
    float* Ps = Vs + 64*64;         // [128][68]  (m-major)  ~34KB

    const int tid = threadIdx.x;
    const int tx  = tid & 7;        // n / d dim
    const int ty  = tid >> 3;       // m dim (0..15)
    const int bh  = blockIdx.x;     // 0..63
    const int qt  = (int)(gridDim.y - 1u - blockIdx.y);  // heavy tiles first
    const int q0  = qt * 128;

    const float* qp = g_q + bh * (LEN*HDIM);
    const float* kp = g_k + bh * (LEN*HDIM);
    const float* vp = g_v + bh * (LEN*HDIM);

    // Load Q tile transposed: Qs[d][m]
    #pragma unroll
    for (int i = 0; i < 16; ++i) {
        float4 v = *(const float4*)(qp + (q0 + tid)*HDIM + i*4);
        Qs[(i*4+0)*128 + tid] = v.x;
        Qs[(i*4+1)*128 + tid] = v.y;
        Qs[(i*4+2)*128 + tid] = v.z;
        Qs[(i*4+3)*128 + tid] = v.w;
    }

    float O[8][8];
    float mrow[8], lrow[8];
    #pragma unroll
    for (int i = 0; i < 8; ++i) {
        mrow[i] = -1e30f; lrow[i] = 0.0f;
        #pragma unroll
        for (int j = 0; j < 8; ++j) O[i][j] = 0.0f;
    }

    const int nkt = 2*qt + 2;     // causal: only tiles with k0 <= q0+127
    for (int kt = 0; kt < nkt; ++kt) {
        const int k0 = kt * 64;
        __syncthreads();  // previous iter's Ks/Vs/Ps reads done (also covers Qs 1st iter)

        // Load K transposed (Ks[d][n]) + V direct (Vs[n][d])
        #pragma unroll
        for (int i = 0; i < 8; ++i) {
            const int f  = tid + i*128;   // 0..1023
            const int r  = f & 63;
            const int d4 = f >> 6;        // 0..15
            float4 v = *(const float4*)(kp + (k0 + r)*HDIM + d4*4);
            Ks[(d4*4+0)*64 + r] = v.x;
            Ks[(d4*4+1)*64 + r] = v.y;
            Ks[(d4*4+2)*64 + r] = v.z;
            Ks[(d4*4+3)*64 + r] = v.w;
            *(float4*)(Vs + f*4) = *(const float4*)(vp + k0*HDIM + f*4);
        }
        __syncthreads();

        // S = Q K^T  (8x8 per thread)
        float s[8][8];
        #pragma unroll
        for (int i = 0; i < 8; ++i)
            #pragma unroll
            for (int j = 0; j < 8; ++j) s[i][j] = 0.0f;

        #pragma unroll 4
        for (int d = 0; d < 64; ++d) {
            float4 a0 = *(const float4*)(Qs + d*128 + ty*8);
            float4 a1 = *(const float4*)(Qs + d*128 + ty*8 + 4);
            float4 b0 = *(const float4*)(Ks + d*64  + tx*8);
            float4 b1 = *(const float4*)(Ks + d*64  + tx*8 + 4);
            float av[8] = {a0.x,a0.y,a0.z,a0.w,a1.x,a1.y,a1.z,a1.w};
            float bv[8] = {b0.x,b0.y,b0.z,b0.w,b1.x,b1.y,b1.z,b1.w};
            #pragma unroll
            for (int i = 0; i < 8; ++i)
                #pragma unroll
                for (int j = 0; j < 8; ++j)
                    s[i][j] = fmaf(av[i], bv[j], s[i][j]);
        }

        // scale + causal mask + online softmax (rows owned by 8 lanes: tx)
        const bool edge = (k0 + 63 > q0);   // uniform per (block, kt)
        #pragma unroll
        for (int i = 0; i < 8; ++i) {
            const int qi = q0 + ty*8 + i;
            float mx = -1e30f;
            #pragma unroll
            for (int j = 0; j < 8; ++j) {
                float v = s[i][j] * 0.125f;
                if (edge && (k0 + tx*8 + j > qi)) v = -1e30f;
                s[i][j] = v;
                mx = fmaxf(mx, v);
            }
            mx = fmaxf(mx, __shfl_xor_sync(0xffffffffu, mx, 1));
            mx = fmaxf(mx, __shfl_xor_sync(0xffffffffu, mx, 2));
            mx = fmaxf(mx, __shfl_xor_sync(0xffffffffu, mx, 4));
            const float mnew = fmaxf(mrow[i], mx);
            const float corr = __expf(mrow[i] - mnew);
            mrow[i] = mnew;
            float rs = 0.0f;
            #pragma unroll
            for (int j = 0; j < 8; ++j) {
                float p = __expf(s[i][j] - mnew);
                s[i][j] = p;
                rs += p;
            }
            rs += __shfl_xor_sync(0xffffffffu, rs, 1);
            rs += __shfl_xor_sync(0xffffffffu, rs, 2);
            rs += __shfl_xor_sync(0xffffffffu, rs, 4);
            lrow[i] = lrow[i] * corr + rs;
            #pragma unroll
            for (int j = 0; j < 8; ++j) O[i][j] *= corr;
        }

        // stage P (m-major, pad 68)
        #pragma unroll
        for (int i = 0; i < 8; ++i) {
            float* pr = Ps + (ty*8 + i)*68 + tx*8;
            *(float4*)(pr)     = make_float4(s[i][0],s[i][1],s[i][2],s[i][3]);
            *(float4*)(pr + 4) = make_float4(s[i][4],s[i][5],s[i][6],s[i][7]);
        }
        __syncthreads();

        // O += P V
        #pragma unroll 4
        for (int n = 0; n < 64; ++n) {
            float4 b0 = *(const float4*)(Vs + n*64 + tx*8);
            float4 b1 = *(const float4*)(Vs + n*64 + tx*8 + 4);
            float bv[8] = {b0.x,b0.y,b0.z,b0.w,b1.x,b1.y,b1.z,b1.w};
            float av[8];
            #pragma unroll
            for (int i = 0; i < 8; ++i) av[i] = Ps[(ty*8 + i)*68 + n];
            #pragma unroll
            for (int i = 0; i < 8; ++i)
                #pragma unroll
                for (int j = 0; j < 8; ++j)
                    O[i][j] = fmaf(av[i], bv[j], O[i][j]);
        }
    }

    // epilogue: normalize, write out[b][l][h*64+d]
    const int b = bh >> 3;
    const int h = bh & 7;
    #pragma unroll
    for (int i = 0; i < 8; ++i) {
        const float inv = 1.0f / lrow[i];
        const int l = q0 + ty*8 + i;
        float* orow = out + ((b*LEN + l) * HD) + h*HDIM + tx*8;
        *(float4*)(orow)     = make_float4(O[i][0]*inv, O[i][1]*inv, O[i][2]*inv, O[i][3]*inv);
        *(float4*)(orow + 4) = make_float4(O[i][4]*inv, O[i][5]*inv, O[i][6]*inv, O[i][7]*inv);
    }
}

// ---------------------------------------------------------------------------
extern "C" void kernel_launch(void* const* d_in, const int* in_sizes, int n_in,
                              void* d_out, int out_size)
{
    (void)in_sizes; (void)n_in; (void)out_size;
    const float* Qseq = (const float*)d_in[0];
    const float* Kseq = (const float*)d_in[1];
    const float* Vseq = (const float*)d_in[2];
    const float* WQ   = (const float*)d_in[3];
    const float* WK   = (const float*)d_in[4];
    const float* WV   = (const float*)d_in[5];
    float* out = (float*)d_out;

    float *gq = nullptr, *gk = nullptr, *gv = nullptr;
    cudaGetSymbolAddress((void**)&gq, g_q);
    cudaGetSymbolAddress((void**)&gk, g_k);
    cudaGetSymbolAddress((void**)&gv, g_v);

    dim3 pgrid(HD/128, (BATCH*LEN)/128);   // (4, 64)
    proj_kernel<<<pgrid, 256>>>(Qseq, WQ, gq);
    proj_kernel<<<pgrid, 256>>>(Kseq, WK, gk);
    proj_kernel<<<pgrid, 256>>>(Vseq, WV, gv);

    const int smem = (64*128 + 64*64 + 64*64 + 128*68) * (int)sizeof(float);
    cudaFuncSetAttribute(attn_kernel, cudaFuncAttributeMaxDynamicSharedMemorySize, smem);
    attn_kernel<<<dim3(BATCH*NHEAD, LEN/128), 128, smem>>>(out);
}

// round 4
// speedup vs baseline: 1.0487x; 1.0487x over previous
#include <cuda_runtime.h>
#include <math.h>

#define BATCH 8
#define LEN   1024
#define DIN   512
#define NHEAD 8
#define HDIM  64
#define HD    512   // NHEAD*HDIM

// Scratch: q,k,v in [B,H,L,64] layout (device globals; no allocation allowed)
__device__ float g_q[BATCH*NHEAD*LEN*HDIM];
__device__ float g_k[BATCH*NHEAD*LEN*HDIM];
__device__ float g_v[BATCH*NHEAD*LEN*HDIM];

typedef unsigned long long u64;

// ---- packed f32x2 helpers (FFMA2 path, sm_103a) ----
__device__ __forceinline__ u64 bcast2(float x) {
    u64 r; unsigned u = __float_as_uint(x);
    asm("mov.b64 %0, {%1, %1};" : "=l"(r) : "r"(u));
    return r;
}
__device__ __forceinline__ void ffma2(u64& d, u64 a, u64 b) {
    asm("fma.rn.f32x2 %0, %1, %2, %0;" : "+l"(d) : "l"(a), "l"(b));
}
__device__ __forceinline__ void fmul2(u64& d, u64 a, u64 b) {
    asm("mul.rn.f32x2 %0, %1, %2;" : "=l"(d) : "l"(a), "l"(b));
}
__device__ __forceinline__ float2 unpack2(u64 v) {
    unsigned lo, hi;
    asm("mov.b64 {%0, %1}, %2;" : "=r"(lo), "=r"(hi) : "l"(v));
    return make_float2(__uint_as_float(lo), __uint_as_float(hi));
}

// ---------------------------------------------------------------------------
// Fused QKV projection GEMM (gridDim.z selects Q/K/V):
// out[b,h,l,d] = sum_k X[b*L+l][k] * W[k][h*64+d]
// BM=128, BN=128, BK=16, 256 threads, 8x8 microtile (packed over n),
// reg-prefetch double buffer.
// ---------------------------------------------------------------------------
__global__ __launch_bounds__(256) void proj3_kernel(
    const float* __restrict__ Xq, const float* __restrict__ Xk, const float* __restrict__ Xv,
    const float* __restrict__ Wq, const float* __restrict__ Wk, const float* __restrict__ Wv)
{
    __shared__ __align__(16) float As[16][128];    // [k][m]
    __shared__ __align__(16) float Bs[16][132];    // [k][n] (pad 132)

    const float* X; const float* W; float* outBHLD;
    if (blockIdx.z == 0)      { X = Xq; W = Wq; outBHLD = g_q; }
    else if (blockIdx.z == 1) { X = Xk; W = Wk; outBHLD = g_k; }
    else                      { X = Xv; W = Wv; outBHLD = g_v; }

    const int tid = threadIdx.x;
    const int tx  = tid & 15;        // n-dim thread coord
    const int ty  = tid >> 4;        // m-dim thread coord
    const int m0  = blockIdx.y * 128;
    const int n0  = blockIdx.x * 128;

    const int a_row = tid >> 1;
    const int a_k0  = (tid & 1) * 8;
    const int b_k = tid >> 5;
    const int b_n = (tid & 31) * 4;

    const float* Ag = X + (m0 + a_row) * DIN + a_k0;
    const float* Bg = W + b_k * HD + n0 + b_n;

    float4 pa0 = *(const float4*)(Ag);
    float4 pa1 = *(const float4*)(Ag + 4);
    float4 pb0 = *(const float4*)(Bg);
    float4 pb1 = *(const float4*)(Bg + 8*HD);

    u64 acc2[8][4];
    #pragma unroll
    for (int i = 0; i < 8; ++i)
        #pragma unroll
        for (int j = 0; j < 4; ++j) acc2[i][j] = 0ull;

    const int NKT = DIN / 16;  // 32
    for (int kt = 0; kt < NKT; ++kt) {
        As[a_k0+0][a_row] = pa0.x; As[a_k0+1][a_row] = pa0.y;
        As[a_k0+2][a_row] = pa0.z; As[a_k0+3][a_row] = pa0.w;
        As[a_k0+4][a_row] = pa1.x; As[a_k0+5][a_row] = pa1.y;
        As[a_k0+6][a_row] = pa1.z; As[a_k0+7][a_row] = pa1.w;
        *(float4*)&Bs[b_k][b_n]     = pb0;
        *(float4*)&Bs[b_k+8][b_n]   = pb1;
        __syncthreads();

        if (kt + 1 < NKT) {
            const float* Ag2 = Ag + (kt+1)*16;
            const float* Bg2 = Bg + (kt+1)*16*HD;
            pa0 = *(const float4*)(Ag2);
            pa1 = *(const float4*)(Ag2 + 4);
            pb0 = *(const float4*)(Bg2);
            pb1 = *(const float4*)(Bg2 + 8*HD);
        }

        #pragma unroll 8
        for (int k = 0; k < 16; ++k) {
            float4 a0 = *(const float4*)&As[k][ty*8];
            float4 a1 = *(const float4*)&As[k][ty*8+4];
            ulonglong2 b01 = *(const ulonglong2*)&Bs[k][tx*8];
            ulonglong2 b23 = *(const ulonglong2*)&Bs[k][tx*8+4];
            u64 bv[4] = {b01.x, b01.y, b23.x, b23.y};
            float av[8] = {a0.x,a0.y,a0.z,a0.w,a1.x,a1.y,a1.z,a1.w};
            #pragma unroll
            for (int i = 0; i < 8; ++i) {
                u64 aa = bcast2(av[i]);
                #pragma unroll
                for (int j = 0; j < 4; ++j)
                    ffma2(acc2[i][j], aa, bv[j]);
            }
        }
        __syncthreads();
    }

    const int h  = (n0 + tx*8) >> 6;
    const int d0 = (n0 + tx*8) & 63;
    #pragma unroll
    for (int i = 0; i < 8; ++i) {
        const int m = m0 + ty*8 + i;
        const int b = m >> 10;
        const int l = m & 1023;
        float* orow = outBHLD + (((b*NHEAD + h)*LEN + l) * HDIM) + d0;
        float2 p0 = unpack2(acc2[i][0]);
        float2 p1 = unpack2(acc2[i][1]);
        float2 p2 = unpack2(acc2[i][2]);
        float2 p3 = unpack2(acc2[i][3]);
        *(float4*)(orow)     = make_float4(p0.x, p0.y, p1.x, p1.y);
        *(float4*)(orow + 4) = make_float4(p2.x, p2.y, p3.x, p3.y);
    }
}

// ---------------------------------------------------------------------------
// Causal flash attention, fp32, packed FFMA2.
// Block: 128 threads, BM=128 queries, BN=64 keys/iter, D=64.
// Thread grid 16(m) x 8(n/d), 8x8 microtiles packed over the n/d dimension.
// ---------------------------------------------------------------------------
__global__ __launch_bounds__(128) void attn_kernel(float* __restrict__ out)
{
    extern __shared__ __align__(16) float sm[];
    float* Qs = sm;                 // [64][128]  (d-major)  32KB
    float* Ks = Qs + 64*128;        // [64][64]   (d-major)  16KB
    float* Vs = Ks + 64*64;         // [64][64]   (n-major)  16KB
    float* Ps = Vs + 64*64;         // [128][68]  (m-major)  ~34KB

    const int tid = threadIdx.x;
    const int tx  = tid & 7;        // n / d dim
    const int ty  = tid >> 3;       // m dim (0..15)
    const int bh  = blockIdx.x;     // 0..63
    const int qt  = (int)(gridDim.y - 1u - blockIdx.y);  // heavy tiles first
    const int q0  = qt * 128;

    const float* qp = g_q + bh * (LEN*HDIM);
    const float* kp = g_k + bh * (LEN*HDIM);
    const float* vp = g_v + bh * (LEN*HDIM);

    // Load Q tile transposed: Qs[d][m]
    #pragma unroll
    for (int i = 0; i < 16; ++i) {
        float4 v = *(const float4*)(qp + (q0 + tid)*HDIM + i*4);
        Qs[(i*4+0)*128 + tid] = v.x;
        Qs[(i*4+1)*128 + tid] = v.y;
        Qs[(i*4+2)*128 + tid] = v.z;
        Qs[(i*4+3)*128 + tid] = v.w;
    }

    u64 O2[8][4];
    float mrow[8], lrow[8];
    #pragma unroll
    for (int i = 0; i < 8; ++i) {
        mrow[i] = -1e30f; lrow[i] = 0.0f;
        #pragma unroll
        for (int j = 0; j < 4; ++j) O2[i][j] = 0ull;
    }

    const int nkt = 2*qt + 2;     // causal: only tiles with k0 <= q0+127
    for (int kt = 0; kt < nkt; ++kt) {
        const int k0 = kt * 64;
        __syncthreads();  // previous iter's Ks/Vs/Ps reads done (also covers Qs 1st iter)

        // Load K transposed (Ks[d][n]) + V direct (Vs[n][d])
        #pragma unroll
        for (int i = 0; i < 8; ++i) {
            const int f  = tid + i*128;   // 0..1023
            const int r  = f & 63;
            const int d4 = f >> 6;        // 0..15
            float4 v = *(const float4*)(kp + (k0 + r)*HDIM + d4*4);
            Ks[(d4*4+0)*64 + r] = v.x;
            Ks[(d4*4+1)*64 + r] = v.y;
            Ks[(d4*4+2)*64 + r] = v.z;
            Ks[(d4*4+3)*64 + r] = v.w;
            *(float4*)(Vs + f*4) = *(const float4*)(vp + k0*HDIM + f*4);
        }
        __syncthreads();

        // S = Q K^T  (8x8 per thread, packed over n)
        u64 s2[8][4];
        #pragma unroll
        for (int i = 0; i < 8; ++i)
            #pragma unroll
            for (int j = 0; j < 4; ++j) s2[i][j] = 0ull;

        #pragma unroll 4
        for (int d = 0; d < 64; ++d) {
            float4 a0 = *(const float4*)(Qs + d*128 + ty*8);
            float4 a1 = *(const float4*)(Qs + d*128 + ty*8 + 4);
            ulonglong2 b01 = *(const ulonglong2*)(Ks + d*64 + tx*8);
            ulonglong2 b23 = *(const ulonglong2*)(Ks + d*64 + tx*8 + 4);
            u64 bv[4] = {b01.x, b01.y, b23.x, b23.y};
            float av[8] = {a0.x,a0.y,a0.z,a0.w,a1.x,a1.y,a1.z,a1.w};
            #pragma unroll
            for (int i = 0; i < 8; ++i) {
                u64 aa = bcast2(av[i]);
                #pragma unroll
                for (int j = 0; j < 4; ++j)
                    ffma2(s2[i][j], aa, bv[j]);
            }
        }

        // scale + causal mask + online softmax, per row (8 lanes share a row)
        const bool edge = (k0 + 63 > q0);   // uniform per (block, kt)
        #pragma unroll
        for (int i = 0; i < 8; ++i) {
            float r[8];
            float2 t;
            t = unpack2(s2[i][0]); r[0] = t.x; r[1] = t.y;
            t = unpack2(s2[i][1]); r[2] = t.x; r[3] = t.y;
            t = unpack2(s2[i][2]); r[4] = t.x; r[5] = t.y;
            t = unpack2(s2[i][3]); r[6] = t.x; r[7] = t.y;

            const int qi = q0 + ty*8 + i;
            float mx = -1e30f;
            #pragma unroll
            for (int j = 0; j < 8; ++j) {
                float v = r[j] * 0.125f;
                if (edge && (k0 + tx*8 + j > qi)) v = -1e30f;
                r[j] = v;
                mx = fmaxf(mx, v);
            }
            mx = fmaxf(mx, __shfl_xor_sync(0xffffffffu, mx, 1));
            mx = fmaxf(mx, __shfl_xor_sync(0xffffffffu, mx, 2));
            mx = fmaxf(mx, __shfl_xor_sync(0xffffffffu, mx, 4));
            const float mnew = fmaxf(mrow[i], mx);
            const float corr = __expf(mrow[i] - mnew);
            mrow[i] = mnew;
            float rs = 0.0f;
            #pragma unroll
            for (int j = 0; j < 8; ++j) {
                float p = __expf(r[j] - mnew);
                r[j] = p;
                rs += p;
            }
            rs += __shfl_xor_sync(0xffffffffu, rs, 1);
            rs += __shfl_xor_sync(0xffffffffu, rs, 2);
            rs += __shfl_xor_sync(0xffffffffu, rs, 4);
            lrow[i] = lrow[i] * corr + rs;

            // stage P row (m-major, pad 68)
            float* pr = Ps + (ty*8 + i)*68 + tx*8;
            *(float4*)(pr)     = make_float4(r[0], r[1], r[2], r[3]);
            *(float4*)(pr + 4) = make_float4(r[4], r[5], r[6], r[7]);

            // O *= corr (packed)
            u64 c2 = bcast2(corr);
            #pragma unroll
            for (int j = 0; j < 4; ++j)
                fmul2(O2[i][j], O2[i][j], c2);
        }
        __syncthreads();

        // O += P V  (packed over d)
        #pragma unroll 4
        for (int n = 0; n < 64; ++n) {
            ulonglong2 b01 = *(const ulonglong2*)(Vs + n*64 + tx*8);
            ulonglong2 b23 = *(const ulonglong2*)(Vs + n*64 + tx*8 + 4);
            u64 bv[4] = {b01.x, b01.y, b23.x, b23.y};
            #pragma unroll
            for (int i = 0; i < 8; ++i) {
                u64 aa = bcast2(Ps[(ty*8 + i)*68 + n]);
                #pragma unroll
                for (int j = 0; j < 4; ++j)
                    ffma2(O2[i][j], aa, bv[j]);
            }
        }
    }

    // epilogue: normalize, write out[b][l][h*64+d]
    const int b = bh >> 3;
    const int h = bh & 7;
    #pragma unroll
    for (int i = 0; i < 8; ++i) {
        const float inv = 1.0f / lrow[i];
        const int l = q0 + ty*8 + i;
        float* orow = out + ((b*LEN + l) * HD) + h*HDIM + tx*8;
        float2 p0 = unpack2(O2[i][0]);
        float2 p1 = unpack2(O2[i][1]);
        float2 p2 = unpack2(O2[i][2]);
        float2 p3 = unpack2(O2[i][3]);
        *(float4*)(orow)     = make_float4(p0.x*inv, p0.y*inv, p1.x*inv, p1.y*inv);
        *(float4*)(orow + 4) = make_float4(p2.x*inv, p2.y*inv, p3.x*inv, p3.y*inv);
    }
}

// ---------------------------------------------------------------------------
extern "C" void kernel_launch(void* const* d_in, const int* in_sizes, int n_in,
                              void* d_out, int out_size)
{
    (void)in_sizes; (void)n_in; (void)out_size;
    const float* Qseq = (const float*)d_in[0];
    const float* Kseq = (const float*)d_in[1];
    const float* Vseq = (const float*)d_in[2];
    const float* WQ   = (const float*)d_in[3];
    const float* WK   = (const float*)d_in[4];
    const float* WV   = (const float*)d_in[5];
    float* out = (float*)d_out;

    dim3 pgrid(HD/128, (BATCH*LEN)/128, 3);   // (4, 64, 3)
    proj3_kernel<<<pgrid, 256>>>(Qseq, Kseq, Vseq, WQ, WK, WV);

    const int smem = (64*128 + 64*64 + 64*64 + 128*68) * (int)sizeof(float);
    cudaFuncSetAttribute(attn_kernel, cudaFuncAttributeMaxDynamicSharedMemorySize, smem);
    attn_kernel<<<dim3(BATCH*NHEAD, LEN/128), 128, smem>>>(out);
}

// round 7
// speedup vs baseline: 1.2822x; 1.2227x over previous
#include <cuda_runtime.h>
#include <cuda_bf16.h>
#include <math.h>
#include <stdint.h>

#define BATCH 8
#define LEN   1024
#define DIN   512
#define NHEAD 8
#define HDIM  64
#define HD    512   // NHEAD*HDIM

// Scratch (device globals; no allocation allowed)
__device__ float g_q[BATCH*NHEAD*LEN*HDIM];
__device__ float g_k[BATCH*NHEAD*LEN*HDIM];
__device__ float g_v[BATCH*NHEAD*LEN*HDIM];
// Pre-split transposed weights: [z][split][n][k] bf16 (stored as u16)
__device__ uint16_t g_wsp[3*3*DIN*HD];

// ===========================================================================
// helpers
// ===========================================================================
__device__ __forceinline__ uint32_t smem_u32(const void* p) {
    uint32_t a;
    asm("{ .reg .u64 t; cvta.to.shared.u64 t, %1; cvt.u32.u64 %0, t; }" : "=r"(a) : "l"(p));
    return a;
}
__device__ __forceinline__ void ldsm_x4(uint32_t* r, uint32_t addr) {
    asm volatile("ldmatrix.sync.aligned.m8n8.x4.shared.b16 {%0,%1,%2,%3}, [%4];"
                 : "=r"(r[0]), "=r"(r[1]), "=r"(r[2]), "=r"(r[3]) : "r"(addr));
}
__device__ __forceinline__ void mma_bf16(float* d, const uint32_t* a, uint32_t b0, uint32_t b1) {
    asm volatile("mma.sync.aligned.m16n8k16.row.col.f32.bf16.bf16.f32 "
                 "{%0,%1,%2,%3}, {%4,%5,%6,%7}, {%8,%9}, {%0,%1,%2,%3};"
                 : "+f"(d[0]), "+f"(d[1]), "+f"(d[2]), "+f"(d[3])
                 : "r"(a[0]), "r"(a[1]), "r"(a[2]), "r"(a[3]), "r"(b0), "r"(b1));
}
__device__ __forceinline__ void split3(float f, uint16_t& h0, uint16_t& h1, uint16_t& h2) {
    __nv_bfloat16 b0 = __float2bfloat16_rn(f);
    float r = f - __bfloat162float(b0);
    __nv_bfloat16 b1 = __float2bfloat16_rn(r);
    r = r - __bfloat162float(b1);
    __nv_bfloat16 b2 = __float2bfloat16_rn(r);
    h0 = __bfloat16_as_ushort(b0);
    h1 = __bfloat16_as_ushort(b1);
    h2 = __bfloat16_as_ushort(b2);
}

// ===========================================================================
// Prep: W transpose + 3-way bf16 split.  g_wsp[z][s][n][k] = split_s(W_z[k][n])
// ===========================================================================
__global__ __launch_bounds__(256) void transpose_split_w(
    const float* __restrict__ WQ, const float* __restrict__ WK, const float* __restrict__ WV)
{
    __shared__ float t[32][33];
    const float* W = (blockIdx.z == 0) ? WQ : (blockIdx.z == 1) ? WK : WV;
    uint16_t* out = g_wsp + blockIdx.z * (3*DIN*HD);
    const int x0 = blockIdx.x * 32, y0 = blockIdx.y * 32;   // x0: n, y0: k
    const int tx = threadIdx.x & 31, ty = threadIdx.x >> 5; // 32 x 8
    #pragma unroll
    for (int j = 0; j < 4; ++j)
        t[ty + j*8][tx] = W[(y0 + ty + j*8)*HD + x0 + tx];
    __syncthreads();
    #pragma unroll
    for (int j = 0; j < 4; ++j) {
        const int n = x0 + ty + j*8;
        const int k = y0 + tx;
        uint16_t h0, h1, h2;
        split3(t[tx][ty + j*8], h0, h1, h2);
        out[0*DIN*HD + n*DIN + k] = h0;
        out[1*DIN*HD + n*DIN + k] = h1;
        out[2*DIN*HD + n*DIN + k] = h2;
    }
}

// ===========================================================================
// Projection GEMM via mma.sync bf16, exact 3-way split (6 cross terms).
// Tile 128x128, 256 threads (warp grid 4m x 2n, each warp 32x64).
// K = 512 in 8 chunks of 64. XOR-swizzled smem tiles (16B granularity).
// smem: A splits 3x16KB + B splits 3x16KB = 96KB.
// ===========================================================================
#define PSM_BYTES (6*16384)

__global__ __launch_bounds__(256, 2) void proj_mma_kernel(
    const float* __restrict__ Xq, const float* __restrict__ Xk, const float* __restrict__ Xv)
{
    extern __shared__ __align__(16) char sm[];   // [A0 A1 A2 B0 B1 B2] x 16KB

    const int tid = threadIdx.x;
    const int z   = blockIdx.z;
    const int n0  = blockIdx.x * 128;
    const int m0  = blockIdx.y * 128;

    const float* X = (z == 0) ? Xq : (z == 1) ? Xk : Xv;
    const uint16_t* wsp = g_wsp + z * (3*DIN*HD);
    float* gdst = (z == 0) ? g_q : (z == 1) ? g_k : g_v;

    const int w      = tid >> 5;
    const int lane   = tid & 31;
    const int warp_m = (w & 3) * 32;
    const int warp_n = (w >> 2) * 64;

    // ldmatrix lane addressing (row-within-16 / half-k select)
    const int rA = lane & 15;
    const int hA = lane >> 4;
    const int rB = (lane & 7) | ((lane >> 4) << 3);
    const int hB = (lane >> 3) & 1;
    const uint32_t smb = smem_u32(sm);

    float acc[2][8][4];
    #pragma unroll
    for (int mf = 0; mf < 2; ++mf)
        #pragma unroll
        for (int nf = 0; nf < 8; ++nf)
            #pragma unroll
            for (int e = 0; e < 4; ++e) acc[mf][nf][e] = 0.0f;

    for (int c = 0; c < 8; ++c) {
        const int c64 = c * 64;
        __syncthreads();   // previous compute done before smem overwrite

        // --- load + split X chunk [128 m][64 k] -> smA[0..2] (swizzled) ---
        #pragma unroll
        for (int i = 0; i < 8; ++i) {
            const int t  = tid + i*256;       // 0..2047 float4s
            const int r  = t >> 4;            // row 0..127
            const int c4 = t & 15;            // float4 index in row (64 floats)
            float4 xv = *(const float4*)(X + (m0 + r)*DIN + c64 + c4*4);
            uint16_t a0[4], a1[4], a2[4];
            split3(xv.x, a0[0], a1[0], a2[0]);
            split3(xv.y, a0[1], a1[1], a2[1]);
            split3(xv.z, a0[2], a1[2], a2[2]);
            split3(xv.w, a0[3], a1[3], a2[3]);
            const uint32_t off = (uint32_t)(r*128 + ((((c4 >> 1) ^ (r & 7))) << 4) + (c4 & 1)*8);
            *(uint2*)(sm + off)         = make_uint2((uint32_t)a0[0] | ((uint32_t)a0[1]<<16),
                                                     (uint32_t)a0[2] | ((uint32_t)a0[3]<<16));
            *(uint2*)(sm + 16384 + off) = make_uint2((uint32_t)a1[0] | ((uint32_t)a1[1]<<16),
                                                     (uint32_t)a1[2] | ((uint32_t)a1[3]<<16));
            *(uint2*)(sm + 32768 + off) = make_uint2((uint32_t)a2[0] | ((uint32_t)a2[1]<<16),
                                                     (uint32_t)a2[2] | ((uint32_t)a2[3]<<16));
        }
        // --- copy pre-split W chunk [128 n][64 k] x3 -> smB (swizzled) ---
        #pragma unroll
        for (int i = 0; i < 12; ++i) {
            const int u   = tid + i*256;      // 0..3071 16B chunks
            const int s   = u >> 10;
            const int rem = u & 1023;
            const int r   = rem >> 3;         // n row 0..127
            const int c16 = rem & 7;          // 16B chunk in row (64 bf16 = 8 chunks)
            const uint4 v = *(const uint4*)(wsp + s*(DIN*HD) + (n0 + r)*DIN + c64 + c16*8);
            const uint32_t off = (uint32_t)(49152 + s*16384 + r*128 + ((c16 ^ (r & 7)) << 4));
            *(uint4*)(sm + off) = v;
        }
        __syncthreads();

        // --- compute: 4 k16-steps x 6 split terms ---
        #pragma unroll
        for (int ks = 0; ks < 4; ++ks) {
            uint32_t a[3][2][4];
            #pragma unroll
            for (int s = 0; s < 3; ++s)
                #pragma unroll
                for (int mf = 0; mf < 2; ++mf) {
                    const uint32_t addr = smb + s*16384
                        + (uint32_t)((warp_m + mf*16 + rA)*128)
                        + (uint32_t)((((ks*2) + hA) ^ (rA & 7)) << 4);
                    ldsm_x4(a[s][mf], addr);
                }
            #pragma unroll
            for (int bj = 0; bj < 3; ++bj) {
                uint32_t bf[4][4];
                #pragma unroll
                for (int nf2 = 0; nf2 < 4; ++nf2) {
                    const uint32_t addr = smb + 49152 + bj*16384
                        + (uint32_t)((warp_n + nf2*16 + rB)*128)
                        + (uint32_t)((((ks*2) + hB) ^ (rB & 7)) << 4);
                    ldsm_x4(bf[nf2], addr);
                }
                #pragma unroll
                for (int ai = 0; ai < 3; ++ai) {
                    if (ai + bj > 2) break;   // keep terms with i+j<=2
                    #pragma unroll
                    for (int mf = 0; mf < 2; ++mf)
                        #pragma unroll
                        for (int nf = 0; nf < 8; ++nf)
                            mma_bf16(acc[mf][nf], a[ai][mf],
                                     bf[nf >> 1][(nf & 1)*2], bf[nf >> 1][(nf & 1)*2 + 1]);
                }
            }
        }
    }

    // --- epilogue: write to g_{q,k,v}[b,h,l,d] ---
    const int g  = lane >> 2;
    const int tc = lane & 3;
    #pragma unroll
    for (int mf = 0; mf < 2; ++mf)
        #pragma unroll
        for (int nf = 0; nf < 8; ++nf) {
            const int mrow = m0 + warp_m + mf*16 + g;
            const int col  = n0 + warp_n + nf*8 + tc*2;
            const int b = mrow >> 10, l = mrow & 1023;
            const int h = col >> 6,   d = col & 63;
            float* base = gdst + (((b*NHEAD + h)*LEN + l))*HDIM + d;
            *(float2*)base = make_float2(acc[mf][nf][0], acc[mf][nf][1]);
            float* base2 = gdst + (((b*NHEAD + h)*LEN + (l + 8)))*HDIM + d;
            *(float2*)base2 = make_float2(acc[mf][nf][2], acc[mf][nf][3]);
        }
}

// ===========================================================================
// Causal flash attention, fp32 scalar (measured best: ~272us).
// ===========================================================================
__global__ __launch_bounds__(128) void attn_kernel(float* __restrict__ out)
{
    extern __shared__ float smf[];
    float* Qs = smf;                // [64][128]
    float* Ks = Qs + 64*128;        // [64][64]
    float* Vs = Ks + 64*64;         // [64][64]
    float* Ps = Vs + 64*64;         // [128][68]

    const int tid = threadIdx.x;
    const int tx  = tid & 7;
    const int ty  = tid >> 3;
    const int bh  = blockIdx.x;
    const int qt  = (int)(gridDim.y - 1u - blockIdx.y);
    const int q0  = qt * 128;

    const float* qp = g_q + bh * (LEN*HDIM);
    const float* kp = g_k + bh * (LEN*HDIM);
    const float* vp = g_v + bh * (LEN*HDIM);

    #pragma unroll
    for (int i = 0; i < 16; ++i) {
        float4 v = *(const float4*)(qp + (q0 + tid)*HDIM + i*4);
        Qs[(i*4+0)*128 + tid] = v.x;
        Qs[(i*4+1)*128 + tid] = v.y;
        Qs[(i*4+2)*128 + tid] = v.z;
        Qs[(i*4+3)*128 + tid] = v.w;
    }

    float O[8][8];
    float mrow[8], lrow[8];
    #pragma unroll
    for (int i = 0; i < 8; ++i) {
        mrow[i] = -1e30f; lrow[i] = 0.0f;
        #pragma unroll
        for (int j = 0; j < 8; ++j) O[i][j] = 0.0f;
    }

    const int nkt = 2*qt + 2;
    for (int kt = 0; kt < nkt; ++kt) {
        const int k0 = kt * 64;
        __syncthreads();

        #pragma unroll
        for (int i = 0; i < 8; ++i) {
            const int f  = tid + i*128;
            const int r  = f & 63;
            const int d4 = f >> 6;
            float4 v = *(const float4*)(kp + (k0 + r)*HDIM + d4*4);
            Ks[(d4*4+0)*64 + r] = v.x;
            Ks[(d4*4+1)*64 + r] = v.y;
            Ks[(d4*4+2)*64 + r] = v.z;
            Ks[(d4*4+3)*64 + r] = v.w;
            *(float4*)(Vs + f*4) = *(const float4*)(vp + k0*HDIM + f*4);
        }
        __syncthreads();

        float s[8][8];
        #pragma unroll
        for (int i = 0; i < 8; ++i)
            #pragma unroll
            for (int j = 0; j < 8; ++j) s[i][j] = 0.0f;

        #pragma unroll 4
        for (int d = 0; d < 64; ++d) {
            float4 a0 = *(const float4*)(Qs + d*128 + ty*8);
            float4 a1 = *(const float4*)(Qs + d*128 + ty*8 + 4);
            float4 b0 = *(const float4*)(Ks + d*64  + tx*8);
            float4 b1 = *(const float4*)(Ks + d*64  + tx*8 + 4);
            float av[8] = {a0.x,a0.y,a0.z,a0.w,a1.x,a1.y,a1.z,a1.w};
            float bv[8] = {b0.x,b0.y,b0.z,b0.w,b1.x,b1.y,b1.z,b1.w};
            #pragma unroll
            for (int i = 0; i < 8; ++i)
                #pragma unroll
                for (int j = 0; j < 8; ++j)
                    s[i][j] = fmaf(av[i], bv[j], s[i][j]);
        }

        const bool edge = (k0 + 63 > q0);
        #pragma unroll
        for (int i = 0; i < 8; ++i) {
            const int qi = q0 + ty*8 + i;
            float mx = -1e30f;
            #pragma unroll
            for (int j = 0; j < 8; ++j) {
                float v = s[i][j] * 0.125f;
                if (edge && (k0 + tx*8 + j > qi)) v = -1e30f;
                s[i][j] = v;
                mx = fmaxf(mx, v);
            }
            mx = fmaxf(mx, __shfl_xor_sync(0xffffffffu, mx, 1));
            mx = fmaxf(mx, __shfl_xor_sync(0xffffffffu, mx, 2));
            mx = fmaxf(mx, __shfl_xor_sync(0xffffffffu, mx, 4));
            const float mnew = fmaxf(mrow[i], mx);
            const float corr = __expf(mrow[i] - mnew);
            mrow[i] = mnew;
            float rs = 0.0f;
            #pragma unroll
            for (int j = 0; j < 8; ++j) {
                float p = __expf(s[i][j] - mnew);
                s[i][j] = p;
                rs += p;
            }
            rs += __shfl_xor_sync(0xffffffffu, rs, 1);
            rs += __shfl_xor_sync(0xffffffffu, rs, 2);
            rs += __shfl_xor_sync(0xffffffffu, rs, 4);
            lrow[i] = lrow[i] * corr + rs;
            #pragma unroll
            for (int j = 0; j < 8; ++j) O[i][j] *= corr;
        }

        #pragma unroll
        for (int i = 0; i < 8; ++i) {
            float* pr = Ps + (ty*8 + i)*68 + tx*8;
            *(float4*)(pr)     = make_float4(s[i][0],s[i][1],s[i][2],s[i][3]);
            *(float4*)(pr + 4) = make_float4(s[i][4],s[i][5],s[i][6],s[i][7]);
        }
        __syncthreads();

        #pragma unroll 4
        for (int n = 0; n < 64; ++n) {
            float4 b0 = *(const float4*)(Vs + n*64 + tx*8);
            float4 b1 = *(const float4*)(Vs + n*64 + tx*8 + 4);
            float bv[8] = {b0.x,b0.y,b0.z,b0.w,b1.x,b1.y,b1.z,b1.w};
            float av[8];
            #pragma unroll
            for (int i = 0; i < 8; ++i) av[i] = Ps[(ty*8 + i)*68 + n];
            #pragma unroll
            for (int i = 0; i < 8; ++i)
                #pragma unroll
                for (int j = 0; j < 8; ++j)
                    O[i][j] = fmaf(av[i], bv[j], O[i][j]);
        }
    }

    const int b = bh >> 3;
    const int h = bh & 7;
    #pragma unroll
    for (int i = 0; i < 8; ++i) {
        const float inv = 1.0f / lrow[i];
        const int l = q0 + ty*8 + i;
        float* orow = out + ((b*LEN + l) * HD) + h*HDIM + tx*8;
        *(float4*)(orow)     = make_float4(O[i][0]*inv, O[i][1]*inv, O[i][2]*inv, O[i][3]*inv);
        *(float4*)(orow + 4) = make_float4(O[i][4]*inv, O[i][5]*inv, O[i][6]*inv, O[i][7]*inv);
    }
}

// ---------------------------------------------------------------------------
extern "C" void kernel_launch(void* const* d_in, const int* in_sizes, int n_in,
                              void* d_out, int out_size)
{
    (void)in_sizes; (void)n_in; (void)out_size;
    const float* Qseq = (const float*)d_in[0];
    const float* Kseq = (const float*)d_in[1];
    const float* Vseq = (const float*)d_in[2];
    const float* WQ   = (const float*)d_in[3];
    const float* WK   = (const float*)d_in[4];
    const float* WV   = (const float*)d_in[5];
    float* out = (float*)d_out;

    transpose_split_w<<<dim3(16,16,3), 256>>>(WQ, WK, WV);

    cudaFuncSetAttribute(proj_mma_kernel, cudaFuncAttributeMaxDynamicSharedMemorySize, PSM_BYTES);
    proj_mma_kernel<<<dim3(4, 64, 3), 256, PSM_BYTES>>>(Qseq, Kseq, Vseq);

    const int smem = (64*128 + 64*64 + 64*64 + 128*68) * (int)sizeof(float);
    cudaFuncSetAttribute(attn_kernel, cudaFuncAttributeMaxDynamicSharedMemorySize, smem);
    attn_kernel<<<dim3(BATCH*NHEAD, LEN/128), 128, smem>>>(out);
}

// round 8
// speedup vs baseline: 1.3198x; 1.0293x over previous
#include <cuda_runtime.h>
#include <cuda_bf16.h>
#include <math.h>
#include <stdint.h>

#define BATCH 8
#define LEN   1024
#define DIN   512
#define NHEAD 8
#define HDIM  64
#define HD    512   // NHEAD*HDIM

// Scratch (device globals; no allocation allowed)
__device__ float g_q[BATCH*NHEAD*LEN*HDIM];
__device__ float g_k[BATCH*NHEAD*LEN*HDIM];
__device__ float g_v[BATCH*NHEAD*LEN*HDIM];
// Pre-split transposed weights: [z][split][n][k] bf16 (stored as u16)
__device__ uint16_t g_wsp[3*3*DIN*HD];

// ===========================================================================
// helpers
// ===========================================================================
__device__ __forceinline__ uint32_t smem_u32(const void* p) {
    uint32_t a;
    asm("{ .reg .u64 t; cvta.to.shared.u64 t, %1; cvt.u32.u64 %0, t; }" : "=r"(a) : "l"(p));
    return a;
}
__device__ __forceinline__ void ldsm_x4(uint32_t* r, uint32_t addr) {
    asm volatile("ldmatrix.sync.aligned.m8n8.x4.shared.b16 {%0,%1,%2,%3}, [%4];"
                 : "=r"(r[0]), "=r"(r[1]), "=r"(r[2]), "=r"(r[3]) : "r"(addr));
}
__device__ __forceinline__ void ldsm_x4_t(uint32_t* r, uint32_t addr) {
    asm volatile("ldmatrix.sync.aligned.m8n8.x4.trans.shared.b16 {%0,%1,%2,%3}, [%4];"
                 : "=r"(r[0]), "=r"(r[1]), "=r"(r[2]), "=r"(r[3]) : "r"(addr));
}
__device__ __forceinline__ void mma_bf16(float* d, const uint32_t* a, uint32_t b0, uint32_t b1) {
    asm volatile("mma.sync.aligned.m16n8k16.row.col.f32.bf16.bf16.f32 "
                 "{%0,%1,%2,%3}, {%4,%5,%6,%7}, {%8,%9}, {%0,%1,%2,%3};"
                 : "+f"(d[0]), "+f"(d[1]), "+f"(d[2]), "+f"(d[3])
                 : "r"(a[0]), "r"(a[1]), "r"(a[2]), "r"(a[3]), "r"(b0), "r"(b1));
}
__device__ __forceinline__ uint32_t pack2(float lo, float hi) {
    uint32_t r;
    asm("cvt.rn.bf16x2.f32 %0, %1, %2;" : "=r"(r) : "f"(hi), "f"(lo));
    return r;
}
__device__ __forceinline__ float bf16lo(float x) {
    return __bfloat162float(__float2bfloat16_rn(x));
}
__device__ __forceinline__ void split3(float f, uint16_t& h0, uint16_t& h1, uint16_t& h2) {
    __nv_bfloat16 b0 = __float2bfloat16_rn(f);
    float r = f - __bfloat162float(b0);
    __nv_bfloat16 b1 = __float2bfloat16_rn(r);
    r = r - __bfloat162float(b1);
    __nv_bfloat16 b2 = __float2bfloat16_rn(r);
    h0 = __bfloat16_as_ushort(b0);
    h1 = __bfloat16_as_ushort(b1);
    h2 = __bfloat16_as_ushort(b2);
}
__device__ __forceinline__ void split2(float f, uint16_t& h0, uint16_t& h1) {
    __nv_bfloat16 b0 = __float2bfloat16_rn(f);
    float r = f - __bfloat162float(b0);
    __nv_bfloat16 b1 = __float2bfloat16_rn(r);
    h0 = __bfloat16_as_ushort(b0);
    h1 = __bfloat16_as_ushort(b1);
}

// ===========================================================================
// Prep: W transpose + 3-way bf16 split.  g_wsp[z][s][n][k] = split_s(W_z[k][n])
// ===========================================================================
__global__ __launch_bounds__(256) void transpose_split_w(
    const float* __restrict__ WQ, const float* __restrict__ WK, const float* __restrict__ WV)
{
    __shared__ float t[32][33];
    const float* W = (blockIdx.z == 0) ? WQ : (blockIdx.z == 1) ? WK : WV;
    uint16_t* out = g_wsp + blockIdx.z * (3*DIN*HD);
    const int x0 = blockIdx.x * 32, y0 = blockIdx.y * 32;   // x0: n, y0: k
    const int tx = threadIdx.x & 31, ty = threadIdx.x >> 5; // 32 x 8
    #pragma unroll
    for (int j = 0; j < 4; ++j)
        t[ty + j*8][tx] = W[(y0 + ty + j*8)*HD + x0 + tx];
    __syncthreads();
    #pragma unroll
    for (int j = 0; j < 4; ++j) {
        const int n = x0 + ty + j*8;
        const int k = y0 + tx;
        uint16_t h0, h1, h2;
        split3(t[tx][ty + j*8], h0, h1, h2);
        out[0*DIN*HD + n*DIN + k] = h0;
        out[1*DIN*HD + n*DIN + k] = h1;
        out[2*DIN*HD + n*DIN + k] = h2;
    }
}

// ===========================================================================
// Projection GEMM via mma.sync bf16, exact 3-way split (6 cross terms).
// (unchanged from R7 — 210us, known good)
// ===========================================================================
#define PSM_BYTES (6*16384)

__global__ __launch_bounds__(256, 2) void proj_mma_kernel(
    const float* __restrict__ Xq, const float* __restrict__ Xk, const float* __restrict__ Xv)
{
    extern __shared__ __align__(16) char sm[];   // [A0 A1 A2 B0 B1 B2] x 16KB

    const int tid = threadIdx.x;
    const int z   = blockIdx.z;
    const int n0  = blockIdx.x * 128;
    const int m0  = blockIdx.y * 128;

    const float* X = (z == 0) ? Xq : (z == 1) ? Xk : Xv;
    const uint16_t* wsp = g_wsp + z * (3*DIN*HD);
    float* gdst = (z == 0) ? g_q : (z == 1) ? g_k : g_v;

    const int w      = tid >> 5;
    const int lane   = tid & 31;
    const int warp_m = (w & 3) * 32;
    const int warp_n = (w >> 2) * 64;

    const int rA = lane & 15;
    const int hA = lane >> 4;
    const int rB = (lane & 7) | ((lane >> 4) << 3);
    const int hB = (lane >> 3) & 1;
    const uint32_t smb = smem_u32(sm);

    float acc[2][8][4];
    #pragma unroll
    for (int mf = 0; mf < 2; ++mf)
        #pragma unroll
        for (int nf = 0; nf < 8; ++nf)
            #pragma unroll
            for (int e = 0; e < 4; ++e) acc[mf][nf][e] = 0.0f;

    for (int c = 0; c < 8; ++c) {
        const int c64 = c * 64;
        __syncthreads();

        #pragma unroll
        for (int i = 0; i < 8; ++i) {
            const int t  = tid + i*256;
            const int r  = t >> 4;
            const int c4 = t & 15;
            float4 xv = *(const float4*)(X + (m0 + r)*DIN + c64 + c4*4);
            uint16_t a0[4], a1[4], a2[4];
            split3(xv.x, a0[0], a1[0], a2[0]);
            split3(xv.y, a0[1], a1[1], a2[1]);
            split3(xv.z, a0[2], a1[2], a2[2]);
            split3(xv.w, a0[3], a1[3], a2[3]);
            const uint32_t off = (uint32_t)(r*128 + ((((c4 >> 1) ^ (r & 7))) << 4) + (c4 & 1)*8);
            *(uint2*)(sm + off)         = make_uint2((uint32_t)a0[0] | ((uint32_t)a0[1]<<16),
                                                     (uint32_t)a0[2] | ((uint32_t)a0[3]<<16));
            *(uint2*)(sm + 16384 + off) = make_uint2((uint32_t)a1[0] | ((uint32_t)a1[1]<<16),
                                                     (uint32_t)a1[2] | ((uint32_t)a1[3]<<16));
            *(uint2*)(sm + 32768 + off) = make_uint2((uint32_t)a2[0] | ((uint32_t)a2[1]<<16),
                                                     (uint32_t)a2[2] | ((uint32_t)a2[3]<<16));
        }
        #pragma unroll
        for (int i = 0; i < 12; ++i) {
            const int u   = tid + i*256;
            const int s   = u >> 10;
            const int rem = u & 1023;
            const int r   = rem >> 3;
            const int c16 = rem & 7;
            const uint4 v = *(const uint4*)(wsp + s*(DIN*HD) + (n0 + r)*DIN + c64 + c16*8);
            const uint32_t off = (uint32_t)(49152 + s*16384 + r*128 + ((c16 ^ (r & 7)) << 4));
            *(uint4*)(sm + off) = v;
        }
        __syncthreads();

        #pragma unroll
        for (int ks = 0; ks < 4; ++ks) {
            uint32_t a[3][2][4];
            #pragma unroll
            for (int s = 0; s < 3; ++s)
                #pragma unroll
                for (int mf = 0; mf < 2; ++mf) {
                    const uint32_t addr = smb + s*16384
                        + (uint32_t)((warp_m + mf*16 + rA)*128)
                        + (uint32_t)((((ks*2) + hA) ^ (rA & 7)) << 4);
                    ldsm_x4(a[s][mf], addr);
                }
            #pragma unroll
            for (int bj = 0; bj < 3; ++bj) {
                uint32_t bf[4][4];
                #pragma unroll
                for (int nf2 = 0; nf2 < 4; ++nf2) {
                    const uint32_t addr = smb + 49152 + bj*16384
                        + (uint32_t)((warp_n + nf2*16 + rB)*128)
                        + (uint32_t)((((ks*2) + hB) ^ (rB & 7)) << 4);
                    ldsm_x4(bf[nf2], addr);
                }
                #pragma unroll
                for (int ai = 0; ai < 3; ++ai) {
                    if (ai + bj > 2) break;
                    #pragma unroll
                    for (int mf = 0; mf < 2; ++mf)
                        #pragma unroll
                        for (int nf = 0; nf < 8; ++nf)
                            mma_bf16(acc[mf][nf], a[ai][mf],
                                     bf[nf >> 1][(nf & 1)*2], bf[nf >> 1][(nf & 1)*2 + 1]);
                }
            }
        }
    }

    const int g  = lane >> 2;
    const int tc = lane & 3;
    #pragma unroll
    for (int mf = 0; mf < 2; ++mf)
        #pragma unroll
        for (int nf = 0; nf < 8; ++nf) {
            const int mrow = m0 + warp_m + mf*16 + g;
            const int col  = n0 + warp_n + nf*8 + tc*2;
            const int b = mrow >> 10, l = mrow & 1023;
            const int h = col >> 6,   d = col & 63;
            float* base = gdst + (((b*NHEAD + h)*LEN + l))*HDIM + d;
            *(float2*)base = make_float2(acc[mf][nf][0], acc[mf][nf][1]);
            float* base2 = gdst + (((b*NHEAD + h)*LEN + (l + 8)))*HDIM + d;
            *(float2*)base2 = make_float2(acc[mf][nf][2], acc[mf][nf][3]);
        }
}

// ===========================================================================
// Causal flash attention via mma.sync bf16 (2-term splits).
// CTA: 128 threads (4 warps), q-tile 64 rows (16/warp), kv chunks of 64.
// smem: Q splits 2x8KB | K splits 2x8KB | V splits 2x8KB = 48KB.
// S = QK^T: 4 products (q0k0,q0k1,q1k0,q1k1). PV: 3 products (p0v0,p0v1,p1v0).
// ===========================================================================
#define ASM_BYTES (48*1024)

__global__ __launch_bounds__(128) void attn_mma_kernel(float* __restrict__ out)
{
    extern __shared__ __align__(16) char sm[];
    const uint32_t smb = smem_u32(sm);
    const uint32_t Kbase = smb + 16384;
    const uint32_t Vbase = smb + 32768;

    const int tid  = threadIdx.x;
    const int lane = tid & 31;
    const int w    = tid >> 5;
    const int bh   = blockIdx.x;                 // 0..63
    const int qt   = 15 - (int)blockIdx.y;       // heavy q-tiles first
    const int q0   = qt * 64;

    const float* qp = g_q + bh * (LEN*HDIM);
    const float* kp = g_k + bh * (LEN*HDIM);
    const float* vp = g_v + bh * (LEN*HDIM);

    const int warp_m = w * 16;
    const int rA = lane & 15;
    const int hA = lane >> 4;
    const int rB = (lane & 7) | ((lane >> 4) << 3);
    const int hB = (lane >> 3) & 1;
    const int g  = lane >> 2;      // row within 8
    const int t4 = lane & 3;       // col pair

    // ---- load + split Q tile (pre-scaled by 1/8) ----
    #pragma unroll
    for (int i = 0; i < 8; ++i) {
        const int t  = tid + i*128;
        const int r  = t >> 4;
        const int c4 = t & 15;
        float4 v = *(const float4*)(qp + (q0 + r)*HDIM + c4*4);
        v.x *= 0.125f; v.y *= 0.125f; v.z *= 0.125f; v.w *= 0.125f;
        uint16_t a0[4], a1[4];
        split2(v.x, a0[0], a1[0]);
        split2(v.y, a0[1], a1[1]);
        split2(v.z, a0[2], a1[2]);
        split2(v.w, a0[3], a1[3]);
        const uint32_t off = (uint32_t)(r*128 + ((((c4 >> 1) ^ (r & 7))) << 4) + (c4 & 1)*8);
        *(uint2*)(sm + off)        = make_uint2((uint32_t)a0[0] | ((uint32_t)a0[1]<<16),
                                                (uint32_t)a0[2] | ((uint32_t)a0[3]<<16));
        *(uint2*)(sm + 8192 + off) = make_uint2((uint32_t)a1[0] | ((uint32_t)a1[1]<<16),
                                                (uint32_t)a1[2] | ((uint32_t)a1[3]<<16));
    }
    __syncthreads();

    // ---- Q fragments into registers (held across all chunks) ----
    uint32_t qf[2][4][4];
    #pragma unroll
    for (int s = 0; s < 2; ++s)
        #pragma unroll
        for (int ks = 0; ks < 4; ++ks) {
            const uint32_t addr = smb + s*8192
                + (uint32_t)((warp_m + rA)*128)
                + (uint32_t)((((ks*2) + hA) ^ (rA & 7)) << 4);
            ldsm_x4(qf[s][ks], addr);
        }

    float O[8][4];
    #pragma unroll
    for (int nf = 0; nf < 8; ++nf)
        #pragma unroll
        for (int e = 0; e < 4; ++e) O[nf][e] = 0.0f;
    float m0 = -1e30f, m1 = -1e30f, l0 = 0.0f, l1 = 0.0f;

    for (int kt = 0; kt <= qt; ++kt) {
        const int k0 = kt * 64;
        __syncthreads();   // protect K/V smem from previous iteration reads

        // ---- load + split K and V chunks ----
        #pragma unroll
        for (int i = 0; i < 8; ++i) {
            const int t  = tid + i*128;
            const int r  = t >> 4;
            const int c4 = t & 15;
            const uint32_t off = (uint32_t)(r*128 + ((((c4 >> 1) ^ (r & 7))) << 4) + (c4 & 1)*8);

            float4 kv = *(const float4*)(kp + (k0 + r)*HDIM + c4*4);
            uint16_t k0s[4], k1s[4];
            split2(kv.x, k0s[0], k1s[0]);
            split2(kv.y, k0s[1], k1s[1]);
            split2(kv.z, k0s[2], k1s[2]);
            split2(kv.w, k0s[3], k1s[3]);
            *(uint2*)(sm + 16384 + off) = make_uint2((uint32_t)k0s[0] | ((uint32_t)k0s[1]<<16),
                                                     (uint32_t)k0s[2] | ((uint32_t)k0s[3]<<16));
            *(uint2*)(sm + 24576 + off) = make_uint2((uint32_t)k1s[0] | ((uint32_t)k1s[1]<<16),
                                                     (uint32_t)k1s[2] | ((uint32_t)k1s[3]<<16));

            float4 vv = *(const float4*)(vp + (k0 + r)*HDIM + c4*4);
            uint16_t v0s[4], v1s[4];
            split2(vv.x, v0s[0], v1s[0]);
            split2(vv.y, v0s[1], v1s[1]);
            split2(vv.z, v0s[2], v1s[2]);
            split2(vv.w, v0s[3], v1s[3]);
            *(uint2*)(sm + 32768 + off) = make_uint2((uint32_t)v0s[0] | ((uint32_t)v0s[1]<<16),
                                                     (uint32_t)v0s[2] | ((uint32_t)v0s[3]<<16));
            *(uint2*)(sm + 40960 + off) = make_uint2((uint32_t)v1s[0] | ((uint32_t)v1s[1]<<16),
                                                     (uint32_t)v1s[2] | ((uint32_t)v1s[3]<<16));
        }
        __syncthreads();

        // ---- S = Q K^T (4 split products) ----
        float c[8][4];
        #pragma unroll
        for (int nf = 0; nf < 8; ++nf)
            #pragma unroll
            for (int e = 0; e < 4; ++e) c[nf][e] = 0.0f;

        #pragma unroll
        for (int ks = 0; ks < 4; ++ks) {
            uint32_t kb[2][4][4];
            #pragma unroll
            for (int s = 0; s < 2; ++s)
                #pragma unroll
                for (int nf2 = 0; nf2 < 4; ++nf2) {
                    const uint32_t addr = Kbase + s*8192
                        + (uint32_t)((nf2*16 + rB)*128)
                        + (uint32_t)((((ks*2) + hB) ^ (rB & 7)) << 4);
                    ldsm_x4(kb[s][nf2], addr);
                }
            #pragma unroll
            for (int sq = 0; sq < 2; ++sq)
                #pragma unroll
                for (int sk = 0; sk < 2; ++sk)
                    #pragma unroll
                    for (int nf = 0; nf < 8; ++nf)
                        mma_bf16(c[nf], qf[sq][ks],
                                 kb[sk][nf >> 1][(nf & 1)*2], kb[sk][nf >> 1][(nf & 1)*2 + 1]);
        }

        // ---- causal mask (diagonal chunk only) ----
        if (kt == qt) {
            #pragma unroll
            for (int nf = 0; nf < 8; ++nf) {
                const int col = nf*8 + t4*2;
                const int r0  = warp_m + g;
                const int r1  = r0 + 8;
                if (col     > r0) c[nf][0] = -1e30f;
                if (col + 1 > r0) c[nf][1] = -1e30f;
                if (col     > r1) c[nf][2] = -1e30f;
                if (col + 1 > r1) c[nf][3] = -1e30f;
            }
        }

        // ---- online softmax on fragments ----
        float mx0 = -1e30f, mx1 = -1e30f;
        #pragma unroll
        for (int nf = 0; nf < 8; ++nf) {
            mx0 = fmaxf(mx0, fmaxf(c[nf][0], c[nf][1]));
            mx1 = fmaxf(mx1, fmaxf(c[nf][2], c[nf][3]));
        }
        mx0 = fmaxf(mx0, __shfl_xor_sync(0xffffffffu, mx0, 1));
        mx0 = fmaxf(mx0, __shfl_xor_sync(0xffffffffu, mx0, 2));
        mx1 = fmaxf(mx1, __shfl_xor_sync(0xffffffffu, mx1, 1));
        mx1 = fmaxf(mx1, __shfl_xor_sync(0xffffffffu, mx1, 2));

        const float mn0 = fmaxf(m0, mx0);
        const float mn1 = fmaxf(m1, mx1);
        const float corr0 = __expf(m0 - mn0);
        const float corr1 = __expf(m1 - mn1);
        m0 = mn0; m1 = mn1;

        float s0 = 0.0f, s1 = 0.0f;
        #pragma unroll
        for (int nf = 0; nf < 8; ++nf) {
            c[nf][0] = __expf(c[nf][0] - mn0); s0 += c[nf][0];
            c[nf][1] = __expf(c[nf][1] - mn0); s0 += c[nf][1];
            c[nf][2] = __expf(c[nf][2] - mn1); s1 += c[nf][2];
            c[nf][3] = __expf(c[nf][3] - mn1); s1 += c[nf][3];
        }
        s0 += __shfl_xor_sync(0xffffffffu, s0, 1);
        s0 += __shfl_xor_sync(0xffffffffu, s0, 2);
        s1 += __shfl_xor_sync(0xffffffffu, s1, 1);
        s1 += __shfl_xor_sync(0xffffffffu, s1, 2);
        l0 = l0*corr0 + s0;
        l1 = l1*corr1 + s1;

        #pragma unroll
        for (int nf = 0; nf < 8; ++nf) {
            O[nf][0] *= corr0; O[nf][1] *= corr0;
            O[nf][2] *= corr1; O[nf][3] *= corr1;
        }

        // ---- O += P V  (P split 2-term from S frags; 3 products) ----
        #pragma unroll
        for (int ks2 = 0; ks2 < 4; ++ks2) {
            const float va = c[2*ks2][0],   vb_ = c[2*ks2][1],
                        vc = c[2*ks2][2],   vd = c[2*ks2][3];
            const float wa = c[2*ks2+1][0], wb = c[2*ks2+1][1],
                        wc = c[2*ks2+1][2], wd = c[2*ks2+1][3];
            uint32_t pa0[4], pa1[4];
            pa0[0] = pack2(va, vb_); pa0[1] = pack2(vc, vd);
            pa0[2] = pack2(wa, wb);  pa0[3] = pack2(wc, wd);
            pa1[0] = pack2(va - bf16lo(va), vb_ - bf16lo(vb_));
            pa1[1] = pack2(vc - bf16lo(vc), vd - bf16lo(vd));
            pa1[2] = pack2(wa - bf16lo(wa), wb - bf16lo(wb));
            pa1[3] = pack2(wc - bf16lo(wc), wd - bf16lo(wd));

            uint32_t vbf[2][4][4];
            const int keyrow = ks2*16 + (lane & 15);
            #pragma unroll
            for (int s = 0; s < 2; ++s)
                #pragma unroll
                for (int dp = 0; dp < 4; ++dp) {
                    const uint32_t addr = Vbase + s*8192
                        + (uint32_t)(keyrow*128)
                        + (uint32_t)(((dp*2 + (lane >> 4)) ^ (keyrow & 7)) << 4);
                    ldsm_x4_t(vbf[s][dp], addr);
                }
            #pragma unroll
            for (int nf = 0; nf < 8; ++nf) {
                const uint32_t b00 = vbf[0][nf >> 1][(nf & 1)*2];
                const uint32_t b01 = vbf[0][nf >> 1][(nf & 1)*2 + 1];
                const uint32_t b10 = vbf[1][nf >> 1][(nf & 1)*2];
                const uint32_t b11 = vbf[1][nf >> 1][(nf & 1)*2 + 1];
                mma_bf16(O[nf], pa0, b00, b01);   // p0 * v0
                mma_bf16(O[nf], pa1, b00, b01);   // p1 * v0
                mma_bf16(O[nf], pa0, b10, b11);   // p0 * v1
            }
        }
    }

    // ---- epilogue ----
    const float inv0 = 1.0f / l0;
    const float inv1 = 1.0f / l1;
    const int b = bh >> 3;
    const int h = bh & 7;
    const int row0 = q0 + warp_m + g;
    const int row1 = row0 + 8;
    #pragma unroll
    for (int nf = 0; nf < 8; ++nf) {
        const int d = nf*8 + t4*2;
        *(float2*)(out + (b*LEN + row0)*HD + h*HDIM + d) =
            make_float2(O[nf][0]*inv0, O[nf][1]*inv0);
        *(float2*)(out + (b*LEN + row1)*HD + h*HDIM + d) =
            make_float2(O[nf][2]*inv1, O[nf][3]*inv1);
    }
}

// ---------------------------------------------------------------------------
extern "C" void kernel_launch(void* const* d_in, const int* in_sizes, int n_in,
                              void* d_out, int out_size)
{
    (void)in_sizes; (void)n_in; (void)out_size;
    const float* Qseq = (const float*)d_in[0];
    const float* Kseq = (const float*)d_in[1];
    const float* Vseq = (const float*)d_in[2];
    const float* WQ   = (const float*)d_in[3];
    const float* WK   = (const float*)d_in[4];
    const float* WV   = (const float*)d_in[5];
    float* out = (float*)d_out;

    transpose_split_w<<<dim3(16,16,3), 256>>>(WQ, WK, WV);

    cudaFuncSetAttribute(proj_mma_kernel, cudaFuncAttributeMaxDynamicSharedMemorySize, PSM_BYTES);
    proj_mma_kernel<<<dim3(4, 64, 3), 256, PSM_BYTES>>>(Qseq, Kseq, Vseq);

    cudaFuncSetAttribute(attn_mma_kernel, cudaFuncAttributeMaxDynamicSharedMemorySize, ASM_BYTES);
    attn_mma_kernel<<<dim3(64, 16), 128, ASM_BYTES>>>(out);
}

// round 9
// speedup vs baseline: 1.8931x; 1.4344x over previous
#include <cuda_runtime.h>
#include <cuda_bf16.h>
#include <math.h>
#include <stdint.h>

#define BATCH 8
#define LEN   1024
#define DIN   512
#define NHEAD 8
#define HDIM  64
#define HD    512   // NHEAD*HDIM

// --- device-global scratch (no allocation allowed) ---
// Pre-split transposed weights: [z][split][n][k] bf16
__device__ uint16_t g_wsp[3*3*DIN*HD];
// Pre-split inputs X: [z][split][m][k] bf16  (m = b*L+l, 8192 rows)
__device__ uint16_t g_xsp[3*3*BATCH*LEN*DIN];
// Split2 bf16 planes of q,k,v: [split][bh][l][d] stored as u32 pairs (d even)
// size each: 2 * 64 * 1024 * 32 u32
#define PLANE_U32 (64*1024*32)
__device__ uint32_t g_qs[2*PLANE_U32];
__device__ uint32_t g_ks[2*PLANE_U32];
__device__ uint32_t g_vs[2*PLANE_U32];

// ===========================================================================
// helpers
// ===========================================================================
__device__ __forceinline__ uint32_t smem_u32(const void* p) {
    uint32_t a;
    asm("{ .reg .u64 t; cvta.to.shared.u64 t, %1; cvt.u32.u64 %0, t; }" : "=r"(a) : "l"(p));
    return a;
}
__device__ __forceinline__ void ldsm_x4(uint32_t* r, uint32_t addr) {
    asm volatile("ldmatrix.sync.aligned.m8n8.x4.shared.b16 {%0,%1,%2,%3}, [%4];"
                 : "=r"(r[0]), "=r"(r[1]), "=r"(r[2]), "=r"(r[3]) : "r"(addr));
}
__device__ __forceinline__ void ldsm_x4_t(uint32_t* r, uint32_t addr) {
    asm volatile("ldmatrix.sync.aligned.m8n8.x4.trans.shared.b16 {%0,%1,%2,%3}, [%4];"
                 : "=r"(r[0]), "=r"(r[1]), "=r"(r[2]), "=r"(r[3]) : "r"(addr));
}
__device__ __forceinline__ void mma_bf16(float* d, const uint32_t* a, uint32_t b0, uint32_t b1) {
    asm volatile("mma.sync.aligned.m16n8k16.row.col.f32.bf16.bf16.f32 "
                 "{%0,%1,%2,%3}, {%4,%5,%6,%7}, {%8,%9}, {%0,%1,%2,%3};"
                 : "+f"(d[0]), "+f"(d[1]), "+f"(d[2]), "+f"(d[3])
                 : "r"(a[0]), "r"(a[1]), "r"(a[2]), "r"(a[3]), "r"(b0), "r"(b1));
}
__device__ __forceinline__ uint32_t pack2(float lo, float hi) {
    uint32_t r;
    asm("cvt.rn.bf16x2.f32 %0, %1, %2;" : "=r"(r) : "f"(hi), "f"(lo));
    return r;
}
__device__ __forceinline__ float bf16lo(float x) {
    return __bfloat162float(__float2bfloat16_rn(x));
}
__device__ __forceinline__ void split3(float f, uint16_t& h0, uint16_t& h1, uint16_t& h2) {
    __nv_bfloat16 b0 = __float2bfloat16_rn(f);
    float r = f - __bfloat162float(b0);
    __nv_bfloat16 b1 = __float2bfloat16_rn(r);
    r = r - __bfloat162float(b1);
    __nv_bfloat16 b2 = __float2bfloat16_rn(r);
    h0 = __bfloat16_as_ushort(b0);
    h1 = __bfloat16_as_ushort(b1);
    h2 = __bfloat16_as_ushort(b2);
}

// ===========================================================================
// Prep 1: W transpose + 3-way bf16 split.  g_wsp[z][s][n][k] = split_s(W_z[k][n])
// ===========================================================================
__global__ __launch_bounds__(256) void transpose_split_w(
    const float* __restrict__ WQ, const float* __restrict__ WK, const float* __restrict__ WV)
{
    __shared__ float t[32][33];
    const float* W = (blockIdx.z == 0) ? WQ : (blockIdx.z == 1) ? WK : WV;
    uint16_t* out = g_wsp + blockIdx.z * (3*DIN*HD);
    const int x0 = blockIdx.x * 32, y0 = blockIdx.y * 32;
    const int tx = threadIdx.x & 31, ty = threadIdx.x >> 5;
    #pragma unroll
    for (int j = 0; j < 4; ++j)
        t[ty + j*8][tx] = W[(y0 + ty + j*8)*HD + x0 + tx];
    __syncthreads();
    #pragma unroll
    for (int j = 0; j < 4; ++j) {
        const int n = x0 + ty + j*8;
        const int k = y0 + tx;
        uint16_t h0, h1, h2;
        split3(t[tx][ty + j*8], h0, h1, h2);
        out[0*DIN*HD + n*DIN + k] = h0;
        out[1*DIN*HD + n*DIN + k] = h1;
        out[2*DIN*HD + n*DIN + k] = h2;
    }
}

// ===========================================================================
// Prep 2: X 3-way bf16 split (streaming).  g_xsp[z][s][m][k]
// ===========================================================================
__global__ __launch_bounds__(256) void split_x(
    const float* __restrict__ Xq, const float* __restrict__ Xk, const float* __restrict__ Xv)
{
    const int z = blockIdx.y;
    const float* X = (z == 0) ? Xq : (z == 1) ? Xk : Xv;
    const int idx = blockIdx.x * 256 + threadIdx.x;        // float4 index, < 1048576
    float4 v = ((const float4*)X)[idx];
    uint16_t a0[4], a1[4], a2[4];
    split3(v.x, a0[0], a1[0], a2[0]);
    split3(v.y, a0[1], a1[1], a2[1]);
    split3(v.z, a0[2], a1[2], a2[2]);
    split3(v.w, a0[3], a1[3], a2[3]);
    uint2* out = (uint2*)g_xsp;
    const int NX4 = BATCH*LEN*DIN/4;                        // uint2 count per plane
    out[(z*3 + 0)*NX4 + idx] = make_uint2((uint32_t)a0[0] | ((uint32_t)a0[1]<<16),
                                          (uint32_t)a0[2] | ((uint32_t)a0[3]<<16));
    out[(z*3 + 1)*NX4 + idx] = make_uint2((uint32_t)a1[0] | ((uint32_t)a1[1]<<16),
                                          (uint32_t)a1[2] | ((uint32_t)a1[3]<<16));
    out[(z*3 + 2)*NX4 + idx] = make_uint2((uint32_t)a2[0] | ((uint32_t)a2[1]<<16),
                                          (uint32_t)a2[2] | ((uint32_t)a2[3]<<16));
}

// ===========================================================================
// Projection GEMM via mma.sync bf16, exact 3-way split (6 cross terms).
// All operands pre-split; epilogue writes split2 bf16 planes (Q scaled 1/8).
// ===========================================================================
#define PSM_BYTES (6*16384)

__global__ __launch_bounds__(256, 2) void proj_mma_kernel()
{
    extern __shared__ __align__(16) char sm[];   // [A0 A1 A2 B0 B1 B2] x 16KB

    const int tid = threadIdx.x;
    const int z   = blockIdx.z;
    const int n0  = blockIdx.x * 128;
    const int m0  = blockIdx.y * 128;

    const uint16_t* xsp = g_xsp + z * (3*BATCH*LEN*DIN);
    const uint16_t* wsp = g_wsp + z * (3*DIN*HD);
    uint32_t* gdst = (z == 0) ? g_qs : (z == 1) ? g_ks : g_vs;
    const float sc = (z == 0) ? 0.125f : 1.0f;

    const int w      = tid >> 5;
    const int lane   = tid & 31;
    const int warp_m = (w & 3) * 32;
    const int warp_n = (w >> 2) * 64;

    const int rA = lane & 15;
    const int hA = lane >> 4;
    const int rB = (lane & 7) | ((lane >> 4) << 3);
    const int hB = (lane >> 3) & 1;
    const uint32_t smb = smem_u32(sm);

    float acc[2][8][4];
    #pragma unroll
    for (int mf = 0; mf < 2; ++mf)
        #pragma unroll
        for (int nf = 0; nf < 8; ++nf)
            #pragma unroll
            for (int e = 0; e < 4; ++e) acc[mf][nf][e] = 0.0f;

    for (int c = 0; c < 8; ++c) {
        const int c64 = c * 64;
        __syncthreads();

        // --- copy pre-split X chunk [128 m][64 k] x3 -> smA (swizzled) ---
        #pragma unroll
        for (int i = 0; i < 12; ++i) {
            const int u   = tid + i*256;      // 0..3071 16B chunks
            const int s   = u >> 10;
            const int rem = u & 1023;
            const int r   = rem >> 3;
            const int c16 = rem & 7;
            const uint4 v = *(const uint4*)(xsp + s*(BATCH*LEN*DIN) + (m0 + r)*DIN + c64 + c16*8);
            const uint32_t off = (uint32_t)(s*16384 + r*128 + ((c16 ^ (r & 7)) << 4));
            *(uint4*)(sm + off) = v;
        }
        // --- copy pre-split W chunk [128 n][64 k] x3 -> smB (swizzled) ---
        #pragma unroll
        for (int i = 0; i < 12; ++i) {
            const int u   = tid + i*256;
            const int s   = u >> 10;
            const int rem = u & 1023;
            const int r   = rem >> 3;
            const int c16 = rem & 7;
            const uint4 v = *(const uint4*)(wsp + s*(DIN*HD) + (n0 + r)*DIN + c64 + c16*8);
            const uint32_t off = (uint32_t)(49152 + s*16384 + r*128 + ((c16 ^ (r & 7)) << 4));
            *(uint4*)(sm + off) = v;
        }
        __syncthreads();

        #pragma unroll
        for (int ks = 0; ks < 4; ++ks) {
            uint32_t a[3][2][4];
            #pragma unroll
            for (int s = 0; s < 3; ++s)
                #pragma unroll
                for (int mf = 0; mf < 2; ++mf) {
                    const uint32_t addr = smb + s*16384
                        + (uint32_t)((warp_m + mf*16 + rA)*128)
                        + (uint32_t)((((ks*2) + hA) ^ (rA & 7)) << 4);
                    ldsm_x4(a[s][mf], addr);
                }
            #pragma unroll
            for (int bj = 0; bj < 3; ++bj) {
                uint32_t bf[4][4];
                #pragma unroll
                for (int nf2 = 0; nf2 < 4; ++nf2) {
                    const uint32_t addr = smb + 49152 + bj*16384
                        + (uint32_t)((warp_n + nf2*16 + rB)*128)
                        + (uint32_t)((((ks*2) + hB) ^ (rB & 7)) << 4);
                    ldsm_x4(bf[nf2], addr);
                }
                #pragma unroll
                for (int ai = 0; ai < 3; ++ai) {
                    if (ai + bj > 2) break;
                    #pragma unroll
                    for (int mf = 0; mf < 2; ++mf)
                        #pragma unroll
                        for (int nf = 0; nf < 8; ++nf)
                            mma_bf16(acc[mf][nf], a[ai][mf],
                                     bf[nf >> 1][(nf & 1)*2], bf[nf >> 1][(nf & 1)*2 + 1]);
                }
            }
        }
    }

    // --- epilogue: split2 -> bf16 planes [s][bh][l][d] ---
    const int g  = lane >> 2;
    const int tc = lane & 3;
    #pragma unroll
    for (int mf = 0; mf < 2; ++mf)
        #pragma unroll
        for (int nf = 0; nf < 8; ++nf) {
            const int mrow = m0 + warp_m + mf*16 + g;
            const int col  = n0 + warp_n + nf*8 + tc*2;
            const int b = mrow >> 10, l = mrow & 1023;
            const int h = col >> 6,   d = col & 63;
            const int bh = b*NHEAD + h;
            #pragma unroll
            for (int half = 0; half < 2; ++half) {
                const float x0 = acc[mf][nf][half*2 + 0] * sc;
                const float x1 = acc[mf][nf][half*2 + 1] * sc;
                const uint32_t lo = pack2(x0, x1);
                const uint32_t hi = pack2(x0 - bf16lo(x0), x1 - bf16lo(x1));
                const int row = l + half*8;
                const uint32_t idx = (uint32_t)((bh*1024 + row)*32 + (d >> 1));
                gdst[idx]             = lo;
                gdst[PLANE_U32 + idx] = hi;
            }
        }
}

// ===========================================================================
// Causal flash attention via mma.sync bf16 (pre-split planes).
// CTA: 128 threads (4 warps), q-tile 64 rows (16/warp), kv chunks of 64.
// smem: Q 2x8KB | K 2x8KB | V 2x8KB = 48KB (swizzled, 128B rows).
// ===========================================================================
#define ASM_BYTES (48*1024)

__global__ __launch_bounds__(128) void attn_mma_kernel(float* __restrict__ out)
{
    extern __shared__ __align__(16) char sm[];
    const uint32_t smb = smem_u32(sm);
    const uint32_t Kbase = smb + 16384;
    const uint32_t Vbase = smb + 32768;

    const int tid  = threadIdx.x;
    const int lane = tid & 31;
    const int w    = tid >> 5;
    const int bh   = blockIdx.x;                 // 0..63
    const int qt   = 15 - (int)blockIdx.y;       // heavy q-tiles first
    const int q0   = qt * 64;

    const uint16_t* qsp = (const uint16_t*)g_qs;
    const uint16_t* ksp = (const uint16_t*)g_ks;
    const uint16_t* vsp = (const uint16_t*)g_vs;
    const int PLANE_U16 = PLANE_U32 * 2;         // u16 elems per plane

    const int warp_m = w * 16;
    const int rA = lane & 15;
    const int hA = lane >> 4;
    const int rB = (lane & 7) | ((lane >> 4) << 3);
    const int hB = (lane >> 3) & 1;
    const int g  = lane >> 2;
    const int t4 = lane & 3;

    // ---- copy Q planes (64 rows x 128B x 2) ----
    #pragma unroll
    for (int i = 0; i < 8; ++i) {
        const int t   = tid + i*128;     // 0..1023 16B chunks
        const int s   = t >> 9;
        const int rem = t & 511;
        const int r   = rem >> 3;
        const int c16 = rem & 7;
        const uint4 v = *(const uint4*)(qsp + s*PLANE_U16 + ((bh*1024 + q0 + r)*64) + c16*8);
        const uint32_t off = (uint32_t)(s*8192 + r*128 + ((c16 ^ (r & 7)) << 4));
        *(uint4*)(sm + off) = v;
    }
    __syncthreads();

    // ---- Q fragments into registers (held across all chunks) ----
    uint32_t qf[2][4][4];
    #pragma unroll
    for (int s = 0; s < 2; ++s)
        #pragma unroll
        for (int ks = 0; ks < 4; ++ks) {
            const uint32_t addr = smb + s*8192
                + (uint32_t)((warp_m + rA)*128)
                + (uint32_t)((((ks*2) + hA) ^ (rA & 7)) << 4);
            ldsm_x4(qf[s][ks], addr);
        }

    float O[8][4];
    #pragma unroll
    for (int nf = 0; nf < 8; ++nf)
        #pragma unroll
        for (int e = 0; e < 4; ++e) O[nf][e] = 0.0f;
    float m0 = -1e30f, m1 = -1e30f, l0 = 0.0f, l1 = 0.0f;

    for (int kt = 0; kt <= qt; ++kt) {
        const int k0 = kt * 64;
        __syncthreads();

        // ---- copy K and V planes for this chunk (4 x 8KB) ----
        #pragma unroll
        for (int i = 0; i < 16; ++i) {
            const int t    = tid + i*128;      // 0..2047 16B chunks
            const int tens = t >> 10;          // 0 = K, 1 = V
            const int rem  = t & 1023;
            const int s    = rem >> 9;
            const int rem2 = rem & 511;
            const int r    = rem2 >> 3;
            const int c16  = rem2 & 7;
            const uint16_t* src = (tens == 0) ? ksp : vsp;
            const uint4 v = *(const uint4*)(src + s*PLANE_U16 + ((bh*1024 + k0 + r)*64) + c16*8);
            const uint32_t off = (uint32_t)(16384 + tens*16384 + s*8192 + r*128
                                            + ((c16 ^ (r & 7)) << 4));
            *(uint4*)(sm + off) = v;
        }
        __syncthreads();

        // ---- S = Q K^T (4 split products) ----
        float c[8][4];
        #pragma unroll
        for (int nf = 0; nf < 8; ++nf)
            #pragma unroll
            for (int e = 0; e < 4; ++e) c[nf][e] = 0.0f;

        #pragma unroll
        for (int ks = 0; ks < 4; ++ks) {
            uint32_t kb[2][4][4];
            #pragma unroll
            for (int s = 0; s < 2; ++s)
                #pragma unroll
                for (int nf2 = 0; nf2 < 4; ++nf2) {
                    const uint32_t addr = Kbase + s*8192
                        + (uint32_t)((nf2*16 + rB)*128)
                        + (uint32_t)((((ks*2) + hB) ^ (rB & 7)) << 4);
                    ldsm_x4(kb[s][nf2], addr);
                }
            #pragma unroll
            for (int sq = 0; sq < 2; ++sq)
                #pragma unroll
                for (int sk = 0; sk < 2; ++sk)
                    #pragma unroll
                    for (int nf = 0; nf < 8; ++nf)
                        mma_bf16(c[nf], qf[sq][ks],
                                 kb[sk][nf >> 1][(nf & 1)*2], kb[sk][nf >> 1][(nf & 1)*2 + 1]);
        }

        // ---- causal mask (diagonal chunk only) ----
        if (kt == qt) {
            #pragma unroll
            for (int nf = 0; nf < 8; ++nf) {
                const int col = nf*8 + t4*2;
                const int r0  = warp_m + g;
                const int r1  = r0 + 8;
                if (col     > r0) c[nf][0] = -1e30f;
                if (col + 1 > r0) c[nf][1] = -1e30f;
                if (col     > r1) c[nf][2] = -1e30f;
                if (col + 1 > r1) c[nf][3] = -1e30f;
            }
        }

        // ---- online softmax on fragments ----
        float mx0 = -1e30f, mx1 = -1e30f;
        #pragma unroll
        for (int nf = 0; nf < 8; ++nf) {
            mx0 = fmaxf(mx0, fmaxf(c[nf][0], c[nf][1]));
            mx1 = fmaxf(mx1, fmaxf(c[nf][2], c[nf][3]));
        }
        mx0 = fmaxf(mx0, __shfl_xor_sync(0xffffffffu, mx0, 1));
        mx0 = fmaxf(mx0, __shfl_xor_sync(0xffffffffu, mx0, 2));
        mx1 = fmaxf(mx1, __shfl_xor_sync(0xffffffffu, mx1, 1));
        mx1 = fmaxf(mx1, __shfl_xor_sync(0xffffffffu, mx1, 2));

        const float mn0 = fmaxf(m0, mx0);
        const float mn1 = fmaxf(m1, mx1);
        const float corr0 = __expf(m0 - mn0);
        const float corr1 = __expf(m1 - mn1);
        m0 = mn0; m1 = mn1;

        float s0 = 0.0f, s1 = 0.0f;
        #pragma unroll
        for (int nf = 0; nf < 8; ++nf) {
            c[nf][0] = __expf(c[nf][0] - mn0); s0 += c[nf][0];
            c[nf][1] = __expf(c[nf][1] - mn0); s0 += c[nf][1];
            c[nf][2] = __expf(c[nf][2] - mn1); s1 += c[nf][2];
            c[nf][3] = __expf(c[nf][3] - mn1); s1 += c[nf][3];
        }
        s0 += __shfl_xor_sync(0xffffffffu, s0, 1);
        s0 += __shfl_xor_sync(0xffffffffu, s0, 2);
        s1 += __shfl_xor_sync(0xffffffffu, s1, 1);
        s1 += __shfl_xor_sync(0xffffffffu, s1, 2);
        l0 = l0*corr0 + s0;
        l1 = l1*corr1 + s1;

        #pragma unroll
        for (int nf = 0; nf < 8; ++nf) {
            O[nf][0] *= corr0; O[nf][1] *= corr0;
            O[nf][2] *= corr1; O[nf][3] *= corr1;
        }

        // ---- O += P V  (P split 2-term from S frags; 3 products) ----
        #pragma unroll
        for (int ks2 = 0; ks2 < 4; ++ks2) {
            const float va = c[2*ks2][0],   vb_ = c[2*ks2][1],
                        vc = c[2*ks2][2],   vd = c[2*ks2][3];
            const float wa = c[2*ks2+1][0], wb = c[2*ks2+1][1],
                        wc = c[2*ks2+1][2], wd = c[2*ks2+1][3];
            uint32_t pa0[4], pa1[4];
            pa0[0] = pack2(va, vb_); pa0[1] = pack2(vc, vd);
            pa0[2] = pack2(wa, wb);  pa0[3] = pack2(wc, wd);
            pa1[0] = pack2(va - bf16lo(va), vb_ - bf16lo(vb_));
            pa1[1] = pack2(vc - bf16lo(vc), vd - bf16lo(vd));
            pa1[2] = pack2(wa - bf16lo(wa), wb - bf16lo(wb));
            pa1[3] = pack2(wc - bf16lo(wc), wd - bf16lo(wd));

            uint32_t vbf[2][4][4];
            const int keyrow = ks2*16 + (lane & 15);
            #pragma unroll
            for (int s = 0; s < 2; ++s)
                #pragma unroll
                for (int dp = 0; dp < 4; ++dp) {
                    const uint32_t addr = Vbase + s*8192
                        + (uint32_t)(keyrow*128)
                        + (uint32_t)(((dp*2 + (lane >> 4)) ^ (keyrow & 7)) << 4);
                    ldsm_x4_t(vbf[s][dp], addr);
                }
            #pragma unroll
            for (int nf = 0; nf < 8; ++nf) {
                const uint32_t b00 = vbf[0][nf >> 1][(nf & 1)*2];
                const uint32_t b01 = vbf[0][nf >> 1][(nf & 1)*2 + 1];
                const uint32_t b10 = vbf[1][nf >> 1][(nf & 1)*2];
                const uint32_t b11 = vbf[1][nf >> 1][(nf & 1)*2 + 1];
                mma_bf16(O[nf], pa0, b00, b01);   // p0 * v0
                mma_bf16(O[nf], pa1, b00, b01);   // p1 * v0
                mma_bf16(O[nf], pa0, b10, b11);   // p0 * v1
            }
        }
    }

    // ---- epilogue ----
    const float inv0 = 1.0f / l0;
    const float inv1 = 1.0f / l1;
    const int b = bh >> 3;
    const int h = bh & 7;
    const int row0 = q0 + warp_m + g;
    const int row1 = row0 + 8;
    #pragma unroll
    for (int nf = 0; nf < 8; ++nf) {
        const int d = nf*8 + t4*2;
        *(float2*)(out + (b*LEN + row0)*HD + h*HDIM + d) =
            make_float2(O[nf][0]*inv0, O[nf][1]*inv0);
        *(float2*)(out + (b*LEN + row1)*HD + h*HDIM + d) =
            make_float2(O[nf][2]*inv1, O[nf][3]*inv1);
    }
}

// ---------------------------------------------------------------------------
extern "C" void kernel_launch(void* const* d_in, const int* in_sizes, int n_in,
                              void* d_out, int out_size)
{
    (void)in_sizes; (void)n_in; (void)out_size;
    const float* Qseq = (const float*)d_in[0];
    const float* Kseq = (const float*)d_in[1];
    const float* Vseq = (const float*)d_in[2];
    const float* WQ   = (const float*)d_in[3];
    const float* WK   = (const float*)d_in[4];
    const float* WV   = (const float*)d_in[5];
    float* out = (float*)d_out;

    transpose_split_w<<<dim3(16,16,3), 256>>>(WQ, WK, WV);
    split_x<<<dim3(BATCH*LEN*DIN/4/256, 3), 256>>>(Qseq, Kseq, Vseq);

    cudaFuncSetAttribute(proj_mma_kernel, cudaFuncAttributeMaxDynamicSharedMemorySize, PSM_BYTES);
    proj_mma_kernel<<<dim3(4, 64, 3), 256, PSM_BYTES>>>();

    cudaFuncSetAttribute(attn_mma_kernel, cudaFuncAttributeMaxDynamicSharedMemorySize, ASM_BYTES);
    attn_mma_kernel<<<dim3(64, 16), 128, ASM_BYTES>>>(out);
}

// round 10
// speedup vs baseline: 1.9788x; 1.0453x over previous
#include <cuda_runtime.h>
#include <cuda_bf16.h>
#include <math.h>
#include <stdint.h>

#define BATCH 8
#define LEN   1024
#define DIN   512
#define NHEAD 8
#define HDIM  64
#define HD    512   // NHEAD*HDIM

// --- device-global scratch (no allocation allowed) ---
// Pre-split transposed weights (2 planes): [z][split][n][k] bf16
__device__ uint16_t g_wsp[3*2*DIN*HD];
// Pre-split inputs X (2 planes): [z][split][m][k] bf16
__device__ uint16_t g_xsp[3*2*BATCH*LEN*DIN];
// Split2 bf16 planes of q,k,v: [split][bh][l][d] stored as u32 pairs (d even)
#define PLANE_U32 (64*1024*32)
__device__ uint32_t g_qs[2*PLANE_U32];
__device__ uint32_t g_ks[2*PLANE_U32];
__device__ uint32_t g_vs[2*PLANE_U32];

// ===========================================================================
// helpers
// ===========================================================================
__device__ __forceinline__ uint32_t smem_u32(const void* p) {
    uint32_t a;
    asm("{ .reg .u64 t; cvta.to.shared.u64 t, %1; cvt.u32.u64 %0, t; }" : "=r"(a) : "l"(p));
    return a;
}
__device__ __forceinline__ void ldsm_x4(uint32_t* r, uint32_t addr) {
    asm volatile("ldmatrix.sync.aligned.m8n8.x4.shared.b16 {%0,%1,%2,%3}, [%4];"
                 : "=r"(r[0]), "=r"(r[1]), "=r"(r[2]), "=r"(r[3]) : "r"(addr));
}
__device__ __forceinline__ void ldsm_x4_t(uint32_t* r, uint32_t addr) {
    asm volatile("ldmatrix.sync.aligned.m8n8.x4.trans.shared.b16 {%0,%1,%2,%3}, [%4];"
                 : "=r"(r[0]), "=r"(r[1]), "=r"(r[2]), "=r"(r[3]) : "r"(addr));
}
__device__ __forceinline__ void mma_bf16(float* d, const uint32_t* a, uint32_t b0, uint32_t b1) {
    asm volatile("mma.sync.aligned.m16n8k16.row.col.f32.bf16.bf16.f32 "
                 "{%0,%1,%2,%3}, {%4,%5,%6,%7}, {%8,%9}, {%0,%1,%2,%3};"
                 : "+f"(d[0]), "+f"(d[1]), "+f"(d[2]), "+f"(d[3])
                 : "r"(a[0]), "r"(a[1]), "r"(a[2]), "r"(a[3]), "r"(b0), "r"(b1));
}
__device__ __forceinline__ uint32_t pack2(float lo, float hi) {
    uint32_t r;
    asm("cvt.rn.bf16x2.f32 %0, %1, %2;" : "=r"(r) : "f"(hi), "f"(lo));
    return r;
}
__device__ __forceinline__ float bf16lo(float x) {
    return __bfloat162float(__float2bfloat16_rn(x));
}
__device__ __forceinline__ void split2(float f, uint16_t& h0, uint16_t& h1) {
    __nv_bfloat16 b0 = __float2bfloat16_rn(f);
    float r = f - __bfloat162float(b0);
    __nv_bfloat16 b1 = __float2bfloat16_rn(r);
    h0 = __bfloat16_as_ushort(b0);
    h1 = __bfloat16_as_ushort(b1);
}

// ===========================================================================
// Prep 1: W transpose + 2-way bf16 split.  g_wsp[z][s][n][k] = split_s(W_z[k][n])
// ===========================================================================
__global__ __launch_bounds__(256) void transpose_split_w(
    const float* __restrict__ WQ, const float* __restrict__ WK, const float* __restrict__ WV)
{
    __shared__ float t[32][33];
    const float* W = (blockIdx.z == 0) ? WQ : (blockIdx.z == 1) ? WK : WV;
    uint16_t* out = g_wsp + blockIdx.z * (2*DIN*HD);
    const int x0 = blockIdx.x * 32, y0 = blockIdx.y * 32;
    const int tx = threadIdx.x & 31, ty = threadIdx.x >> 5;
    #pragma unroll
    for (int j = 0; j < 4; ++j)
        t[ty + j*8][tx] = W[(y0 + ty + j*8)*HD + x0 + tx];
    __syncthreads();
    #pragma unroll
    for (int j = 0; j < 4; ++j) {
        const int n = x0 + ty + j*8;
        const int k = y0 + tx;
        uint16_t h0, h1;
        split2(t[tx][ty + j*8], h0, h1);
        out[0*DIN*HD + n*DIN + k] = h0;
        out[1*DIN*HD + n*DIN + k] = h1;
    }
}

// ===========================================================================
// Prep 2: X 2-way bf16 split (streaming).  g_xsp[z][s][m][k]
// ===========================================================================
__global__ __launch_bounds__(256) void split_x(
    const float* __restrict__ Xq, const float* __restrict__ Xk, const float* __restrict__ Xv)
{
    const int z = blockIdx.y;
    const float* X = (z == 0) ? Xq : (z == 1) ? Xk : Xv;
    const int idx = blockIdx.x * 256 + threadIdx.x;        // float4 index
    float4 v = ((const float4*)X)[idx];
    uint16_t a0[4], a1[4];
    split2(v.x, a0[0], a1[0]);
    split2(v.y, a0[1], a1[1]);
    split2(v.z, a0[2], a1[2]);
    split2(v.w, a0[3], a1[3]);
    uint2* out = (uint2*)g_xsp;
    const int NX4 = BATCH*LEN*DIN/4;
    out[(z*2 + 0)*NX4 + idx] = make_uint2((uint32_t)a0[0] | ((uint32_t)a0[1]<<16),
                                          (uint32_t)a0[2] | ((uint32_t)a0[3]<<16));
    out[(z*2 + 1)*NX4 + idx] = make_uint2((uint32_t)a1[0] | ((uint32_t)a1[1]<<16),
                                          (uint32_t)a1[2] | ((uint32_t)a1[3]<<16));
}

// ===========================================================================
// Projection GEMM via mma.sync bf16, 3 cross terms (i+j<=1).
// Tile 128x128, 256 threads; smem A0,A1,B0,B1 x 16KB = 64KB.
// Epilogue writes split2 bf16 planes (Q scaled 1/8).
// ===========================================================================
#define PSM_BYTES (4*16384)

__global__ __launch_bounds__(256, 3) void proj_mma_kernel()
{
    extern __shared__ __align__(16) char sm[];   // [A0 A1 B0 B1] x 16KB

    const int tid = threadIdx.x;
    const int z   = blockIdx.z;
    const int n0  = blockIdx.x * 128;
    const int m0  = blockIdx.y * 128;

    const uint16_t* xsp = g_xsp + z * (2*BATCH*LEN*DIN);
    const uint16_t* wsp = g_wsp + z * (2*DIN*HD);
    uint32_t* gdst = (z == 0) ? g_qs : (z == 1) ? g_ks : g_vs;
    const float sc = (z == 0) ? 0.125f : 1.0f;

    const int w      = tid >> 5;
    const int lane   = tid & 31;
    const int warp_m = (w & 3) * 32;
    const int warp_n = (w >> 2) * 64;

    const int rA = lane & 15;
    const int hA = lane >> 4;
    const int rB = (lane & 7) | ((lane >> 4) << 3);
    const int hB = (lane >> 3) & 1;
    const uint32_t smb = smem_u32(sm);

    float acc[2][8][4];
    #pragma unroll
    for (int mf = 0; mf < 2; ++mf)
        #pragma unroll
        for (int nf = 0; nf < 8; ++nf)
            #pragma unroll
            for (int e = 0; e < 4; ++e) acc[mf][nf][e] = 0.0f;

    for (int c = 0; c < 8; ++c) {
        const int c64 = c * 64;
        __syncthreads();

        // --- copy pre-split X chunk [128 m][64 k] x2 -> smA (swizzled) ---
        #pragma unroll
        for (int i = 0; i < 8; ++i) {
            const int u   = tid + i*256;      // 0..2047 16B chunks
            const int s   = u >> 10;
            const int rem = u & 1023;
            const int r   = rem >> 3;
            const int c16 = rem & 7;
            const uint4 v = *(const uint4*)(xsp + s*(BATCH*LEN*DIN) + (m0 + r)*DIN + c64 + c16*8);
            const uint32_t off = (uint32_t)(s*16384 + r*128 + ((c16 ^ (r & 7)) << 4));
            *(uint4*)(sm + off) = v;
        }
        // --- copy pre-split W chunk [128 n][64 k] x2 -> smB (swizzled) ---
        #pragma unroll
        for (int i = 0; i < 8; ++i) {
            const int u   = tid + i*256;
            const int s   = u >> 10;
            const int rem = u & 1023;
            const int r   = rem >> 3;
            const int c16 = rem & 7;
            const uint4 v = *(const uint4*)(wsp + s*(DIN*HD) + (n0 + r)*DIN + c64 + c16*8);
            const uint32_t off = (uint32_t)(32768 + s*16384 + r*128 + ((c16 ^ (r & 7)) << 4));
            *(uint4*)(sm + off) = v;
        }
        __syncthreads();

        #pragma unroll
        for (int ks = 0; ks < 4; ++ks) {
            uint32_t a[2][2][4];
            #pragma unroll
            for (int s = 0; s < 2; ++s)
                #pragma unroll
                for (int mf = 0; mf < 2; ++mf) {
                    const uint32_t addr = smb + s*16384
                        + (uint32_t)((warp_m + mf*16 + rA)*128)
                        + (uint32_t)((((ks*2) + hA) ^ (rA & 7)) << 4);
                    ldsm_x4(a[s][mf], addr);
                }
            #pragma unroll
            for (int bj = 0; bj < 2; ++bj) {
                uint32_t bf[4][4];
                #pragma unroll
                for (int nf2 = 0; nf2 < 4; ++nf2) {
                    const uint32_t addr = smb + 32768 + bj*16384
                        + (uint32_t)((warp_n + nf2*16 + rB)*128)
                        + (uint32_t)((((ks*2) + hB) ^ (rB & 7)) << 4);
                    ldsm_x4(bf[nf2], addr);
                }
                #pragma unroll
                for (int ai = 0; ai < 2; ++ai) {
                    if (ai + bj > 1) break;   // terms (0,0),(0,1),(1,0)
                    #pragma unroll
                    for (int mf = 0; mf < 2; ++mf)
                        #pragma unroll
                        for (int nf = 0; nf < 8; ++nf)
                            mma_bf16(acc[mf][nf], a[ai][mf],
                                     bf[nf >> 1][(nf & 1)*2], bf[nf >> 1][(nf & 1)*2 + 1]);
                }
            }
        }
    }

    // --- epilogue: split2 -> bf16 planes [s][bh][l][d] ---
    const int g  = lane >> 2;
    const int tc = lane & 3;
    #pragma unroll
    for (int mf = 0; mf < 2; ++mf)
        #pragma unroll
        for (int nf = 0; nf < 8; ++nf) {
            const int mrow = m0 + warp_m + mf*16 + g;
            const int col  = n0 + warp_n + nf*8 + tc*2;
            const int b = mrow >> 10, l = mrow & 1023;
            const int h = col >> 6,   d = col & 63;
            const int bh = b*NHEAD + h;
            #pragma unroll
            for (int half = 0; half < 2; ++half) {
                const float x0 = acc[mf][nf][half*2 + 0] * sc;
                const float x1 = acc[mf][nf][half*2 + 1] * sc;
                const uint32_t lo = pack2(x0, x1);
                const uint32_t hi = pack2(x0 - bf16lo(x0), x1 - bf16lo(x1));
                const int row = l + half*8;
                const uint32_t idx = (uint32_t)((bh*1024 + row)*32 + (d >> 1));
                gdst[idx]             = lo;
                gdst[PLANE_U32 + idx] = hi;
            }
        }
}

// ===========================================================================
// Causal flash attention via mma.sync bf16 (pre-split planes).
// (unchanged from R9 — 91.4us measured)
// ===========================================================================
#define ASM_BYTES (48*1024)

__global__ __launch_bounds__(128) void attn_mma_kernel(float* __restrict__ out)
{
    extern __shared__ __align__(16) char sm[];
    const uint32_t smb = smem_u32(sm);
    const uint32_t Kbase = smb + 16384;
    const uint32_t Vbase = smb + 32768;

    const int tid  = threadIdx.x;
    const int lane = tid & 31;
    const int w    = tid >> 5;
    const int bh   = blockIdx.x;                 // 0..63
    const int qt   = 15 - (int)blockIdx.y;       // heavy q-tiles first
    const int q0   = qt * 64;

    const uint16_t* qsp = (const uint16_t*)g_qs;
    const uint16_t* ksp = (const uint16_t*)g_ks;
    const uint16_t* vsp = (const uint16_t*)g_vs;
    const int PLANE_U16 = PLANE_U32 * 2;

    const int warp_m = w * 16;
    const int rA = lane & 15;
    const int hA = lane >> 4;
    const int rB = (lane & 7) | ((lane >> 4) << 3);
    const int hB = (lane >> 3) & 1;
    const int g  = lane >> 2;
    const int t4 = lane & 3;

    // ---- copy Q planes (64 rows x 128B x 2) ----
    #pragma unroll
    for (int i = 0; i < 8; ++i) {
        const int t   = tid + i*128;
        const int s   = t >> 9;
        const int rem = t & 511;
        const int r   = rem >> 3;
        const int c16 = rem & 7;
        const uint4 v = *(const uint4*)(qsp + s*PLANE_U16 + ((bh*1024 + q0 + r)*64) + c16*8);
        const uint32_t off = (uint32_t)(s*8192 + r*128 + ((c16 ^ (r & 7)) << 4));
        *(uint4*)(sm + off) = v;
    }
    __syncthreads();

    uint32_t qf[2][4][4];
    #pragma unroll
    for (int s = 0; s < 2; ++s)
        #pragma unroll
        for (int ks = 0; ks < 4; ++ks) {
            const uint32_t addr = smb + s*8192
                + (uint32_t)((warp_m + rA)*128)
                + (uint32_t)((((ks*2) + hA) ^ (rA & 7)) << 4);
            ldsm_x4(qf[s][ks], addr);
        }

    float O[8][4];
    #pragma unroll
    for (int nf = 0; nf < 8; ++nf)
        #pragma unroll
        for (int e = 0; e < 4; ++e) O[nf][e] = 0.0f;
    float m0 = -1e30f, m1 = -1e30f, l0 = 0.0f, l1 = 0.0f;

    for (int kt = 0; kt <= qt; ++kt) {
        const int k0 = kt * 64;
        __syncthreads();

        #pragma unroll
        for (int i = 0; i < 16; ++i) {
            const int t    = tid + i*128;
            const int tens = t >> 10;
            const int rem  = t & 1023;
            const int s    = rem >> 9;
            const int rem2 = rem & 511;
            const int r    = rem2 >> 3;
            const int c16  = rem2 & 7;
            const uint16_t* src = (tens == 0) ? ksp : vsp;
            const uint4 v = *(const uint4*)(src + s*PLANE_U16 + ((bh*1024 + k0 + r)*64) + c16*8);
            const uint32_t off = (uint32_t)(16384 + tens*16384 + s*8192 + r*128
                                            + ((c16 ^ (r & 7)) << 4));
            *(uint4*)(sm + off) = v;
        }
        __syncthreads();

        float c[8][4];
        #pragma unroll
        for (int nf = 0; nf < 8; ++nf)
            #pragma unroll
            for (int e = 0; e < 4; ++e) c[nf][e] = 0.0f;

        #pragma unroll
        for (int ks = 0; ks < 4; ++ks) {
            uint32_t kb[2][4][4];
            #pragma unroll
            for (int s = 0; s < 2; ++s)
                #pragma unroll
                for (int nf2 = 0; nf2 < 4; ++nf2) {
                    const uint32_t addr = Kbase + s*8192
                        + (uint32_t)((nf2*16 + rB)*128)
                        + (uint32_t)((((ks*2) + hB) ^ (rB & 7)) << 4);
                    ldsm_x4(kb[s][nf2], addr);
                }
            #pragma unroll
            for (int sq = 0; sq < 2; ++sq)
                #pragma unroll
                for (int sk = 0; sk < 2; ++sk)
                    #pragma unroll
                    for (int nf = 0; nf < 8; ++nf)
                        mma_bf16(c[nf], qf[sq][ks],
                                 kb[sk][nf >> 1][(nf & 1)*2], kb[sk][nf >> 1][(nf & 1)*2 + 1]);
        }

        if (kt == qt) {
            #pragma unroll
            for (int nf = 0; nf < 8; ++nf) {
                const int col = nf*8 + t4*2;
                const int r0  = warp_m + g;
                const int r1  = r0 + 8;
                if (col     > r0) c[nf][0] = -1e30f;
                if (col + 1 > r0) c[nf][1] = -1e30f;
                if (col     > r1) c[nf][2] = -1e30f;
                if (col + 1 > r1) c[nf][3] = -1e30f;
            }
        }

        float mx0 = -1e30f, mx1 = -1e30f;
        #pragma unroll
        for (int nf = 0; nf < 8; ++nf) {
            mx0 = fmaxf(mx0, fmaxf(c[nf][0], c[nf][1]));
            mx1 = fmaxf(mx1, fmaxf(c[nf][2], c[nf][3]));
        }
        mx0 = fmaxf(mx0, __shfl_xor_sync(0xffffffffu, mx0, 1));
        mx0 = fmaxf(mx0, __shfl_xor_sync(0xffffffffu, mx0, 2));
        mx1 = fmaxf(mx1, __shfl_xor_sync(0xffffffffu, mx1, 1));
        mx1 = fmaxf(mx1, __shfl_xor_sync(0xffffffffu, mx1, 2));

        const float mn0 = fmaxf(m0, mx0);
        const float mn1 = fmaxf(m1, mx1);
        const float corr0 = __expf(m0 - mn0);
        const float corr1 = __expf(m1 - mn1);
        m0 = mn0; m1 = mn1;

        float s0 = 0.0f, s1 = 0.0f;
        #pragma unroll
        for (int nf = 0; nf < 8; ++nf) {
            c[nf][0] = __expf(c[nf][0] - mn0); s0 += c[nf][0];
            c[nf][1] = __expf(c[nf][1] - mn0); s0 += c[nf][1];
            c[nf][2] = __expf(c[nf][2] - mn1); s1 += c[nf][2];
            c[nf][3] = __expf(c[nf][3] - mn1); s1 += c[nf][3];
        }
        s0 += __shfl_xor_sync(0xffffffffu, s0, 1);
        s0 += __shfl_xor_sync(0xffffffffu, s0, 2);
        s1 += __shfl_xor_sync(0xffffffffu, s1, 1);
        s1 += __shfl_xor_sync(0xffffffffu, s1, 2);
        l0 = l0*corr0 + s0;
        l1 = l1*corr1 + s1;

        #pragma unroll
        for (int nf = 0; nf < 8; ++nf) {
            O[nf][0] *= corr0; O[nf][1] *= corr0;
            O[nf][2] *= corr1; O[nf][3] *= corr1;
        }

        #pragma unroll
        for (int ks2 = 0; ks2 < 4; ++ks2) {
            const float va = c[2*ks2][0],   vb_ = c[2*ks2][1],
                        vc = c[2*ks2][2],   vd = c[2*ks2][3];
            const float wa = c[2*ks2+1][0], wb = c[2*ks2+1][1],
                        wc = c[2*ks2+1][2], wd = c[2*ks2+1][3];
            uint32_t pa0[4], pa1[4];
            pa0[0] = pack2(va, vb_); pa0[1] = pack2(vc, vd);
            pa0[2] = pack2(wa, wb);  pa0[3] = pack2(wc, wd);
            pa1[0] = pack2(va - bf16lo(va), vb_ - bf16lo(vb_));
            pa1[1] = pack2(vc - bf16lo(vc), vd - bf16lo(vd));
            pa1[2] = pack2(wa - bf16lo(wa), wb - bf16lo(wb));
            pa1[3] = pack2(wc - bf16lo(wc), wd - bf16lo(wd));

            uint32_t vbf[2][4][4];
            const int keyrow = ks2*16 + (lane & 15);
            #pragma unroll
            for (int s = 0; s < 2; ++s)
                #pragma unroll
                for (int dp = 0; dp < 4; ++dp) {
                    const uint32_t addr = Vbase + s*8192
                        + (uint32_t)(keyrow*128)
                        + (uint32_t)(((dp*2 + (lane >> 4)) ^ (keyrow & 7)) << 4);
                    ldsm_x4_t(vbf[s][dp], addr);
                }
            #pragma unroll
            for (int nf = 0; nf < 8; ++nf) {
                const uint32_t b00 = vbf[0][nf >> 1][(nf & 1)*2];
                const uint32_t b01 = vbf[0][nf >> 1][(nf & 1)*2 + 1];
                const uint32_t b10 = vbf[1][nf >> 1][(nf & 1)*2];
                const uint32_t b11 = vbf[1][nf >> 1][(nf & 1)*2 + 1];
                mma_bf16(O[nf], pa0, b00, b01);
                mma_bf16(O[nf], pa1, b00, b01);
                mma_bf16(O[nf], pa0, b10, b11);
            }
        }
    }

    const float inv0 = 1.0f / l0;
    const float inv1 = 1.0f / l1;
    const int b = bh >> 3;
    const int h = bh & 7;
    const int row0 = q0 + warp_m + g;
    const int row1 = row0 + 8;
    #pragma unroll
    for (int nf = 0; nf < 8; ++nf) {
        const int d = nf*8 + t4*2;
        *(float2*)(out + (b*LEN + row0)*HD + h*HDIM + d) =
            make_float2(O[nf][0]*inv0, O[nf][1]*inv0);
        *(float2*)(out + (b*LEN + row1)*HD + h*HDIM + d) =
            make_float2(O[nf][2]*inv1, O[nf][3]*inv1);
    }
}

// ---------------------------------------------------------------------------
extern "C" void kernel_launch(void* const* d_in, const int* in_sizes, int n_in,
                              void* d_out, int out_size)
{
    (void)in_sizes; (void)n_in; (void)out_size;
    const float* Qseq = (const float*)d_in[0];
    const float* Kseq = (const float*)d_in[1];
    const float* Vseq = (const float*)d_in[2];
    const float* WQ   = (const float*)d_in[3];
    const float* WK   = (const float*)d_in[4];
    const float* WV   = (const float*)d_in[5];
    float* out = (float*)d_out;

    transpose_split_w<<<dim3(16,16,3), 256>>>(WQ, WK, WV);
    split_x<<<dim3(BATCH*LEN*DIN/4/256, 3), 256>>>(Qseq, Kseq, Vseq);

    cudaFuncSetAttribute(proj_mma_kernel, cudaFuncAttributeMaxDynamicSharedMemorySize, PSM_BYTES);
    proj_mma_kernel<<<dim3(4, 64, 3), 256, PSM_BYTES>>>();

    cudaFuncSetAttribute(attn_mma_kernel, cudaFuncAttributeMaxDynamicSharedMemorySize, ASM_BYTES);
    attn_mma_kernel<<<dim3(64, 16), 128, ASM_BYTES>>>(out);
}

// round 13
// speedup vs baseline: 2.8509x; 1.4407x over previous
#include <cuda_runtime.h>
#include <cuda_bf16.h>
#include <math.h>
#include <stdint.h>

#define BATCH 8
#define LEN   1024
#define DIN   512
#define NHEAD 8
#define HDIM  64
#define HD    512   // NHEAD*HDIM

// --- device-global scratch (no allocation allowed) ---
// Pre-split transposed weights (2 planes): [z][split][n][k] bf16
__device__ uint16_t g_wsp[3*2*DIN*HD];
// Pre-split inputs X (2 planes): [z][split][m][k] bf16
__device__ uint16_t g_xsp[3*2*BATCH*LEN*DIN];
// Split2 bf16 planes of q,k,v: [split][bh][l][d] stored as u32 pairs (d even)
#define PLANE_U32 (64*1024*32)
__device__ uint32_t g_qs[2*PLANE_U32];
__device__ uint32_t g_ks[2*PLANE_U32];
__device__ uint32_t g_vs[2*PLANE_U32];

// ===========================================================================
// helpers
// ===========================================================================
__device__ __forceinline__ uint32_t smem_u32(const void* p) {
    uint32_t a;
    asm("{ .reg .u64 t; cvta.to.shared.u64 t, %1; cvt.u32.u64 %0, t; }" : "=r"(a) : "l"(p));
    return a;
}
__device__ __forceinline__ void ldsm_x4(uint32_t* r, uint32_t addr) {
    asm volatile("ldmatrix.sync.aligned.m8n8.x4.shared.b16 {%0,%1,%2,%3}, [%4];"
                 : "=r"(r[0]), "=r"(r[1]), "=r"(r[2]), "=r"(r[3]) : "r"(addr));
}
__device__ __forceinline__ void ldsm_x4_t(uint32_t* r, uint32_t addr) {
    asm volatile("ldmatrix.sync.aligned.m8n8.x4.trans.shared.b16 {%0,%1,%2,%3}, [%4];"
                 : "=r"(r[0]), "=r"(r[1]), "=r"(r[2]), "=r"(r[3]) : "r"(addr));
}
__device__ __forceinline__ void mma_bf16(float* d, const uint32_t* a, uint32_t b0, uint32_t b1) {
    asm volatile("mma.sync.aligned.m16n8k16.row.col.f32.bf16.bf16.f32 "
                 "{%0,%1,%2,%3}, {%4,%5,%6,%7}, {%8,%9}, {%0,%1,%2,%3};"
                 : "+f"(d[0]), "+f"(d[1]), "+f"(d[2]), "+f"(d[3])
                 : "r"(a[0]), "r"(a[1]), "r"(a[2]), "r"(a[3]), "r"(b0), "r"(b1));
}
__device__ __forceinline__ uint32_t pack2(float lo, float hi) {
    uint32_t r;
    asm("cvt.rn.bf16x2.f32 %0, %1, %2;" : "=r"(r) : "f"(hi), "f"(lo));
    return r;
}
__device__ __forceinline__ float bf16lo(float x) {
    return __bfloat162float(__float2bfloat16_rn(x));
}
__device__ __forceinline__ void split2(float f, uint16_t& h0, uint16_t& h1) {
    __nv_bfloat16 b0 = __float2bfloat16_rn(f);
    float r = f - __bfloat162float(b0);
    __nv_bfloat16 b1 = __float2bfloat16_rn(r);
    h0 = __bfloat16_as_ushort(b0);
    h1 = __bfloat16_as_ushort(b1);
}

// ===========================================================================
// Prep 1: W transpose + 2-way bf16 split.  g_wsp[z][s][n][k] = split_s(W_z[k][n])
// ===========================================================================
__global__ __launch_bounds__(256) void transpose_split_w(
    const float* __restrict__ WQ, const float* __restrict__ WK, const float* __restrict__ WV)
{
    __shared__ float t[32][33];
    const float* W = (blockIdx.z == 0) ? WQ : (blockIdx.z == 1) ? WK : WV;
    uint16_t* out = g_wsp + blockIdx.z * (2*DIN*HD);
    const int x0 = blockIdx.x * 32, y0 = blockIdx.y * 32;
    const int tx = threadIdx.x & 31, ty = threadIdx.x >> 5;
    #pragma unroll
    for (int j = 0; j < 4; ++j)
        t[ty + j*8][tx] = W[(y0 + ty + j*8)*HD + x0 + tx];
    __syncthreads();
    #pragma unroll
    for (int j = 0; j < 4; ++j) {
        const int n = x0 + ty + j*8;
        const int k = y0 + tx;
        uint16_t h0, h1;
        split2(t[tx][ty + j*8], h0, h1);
        out[0*DIN*HD + n*DIN + k] = h0;
        out[1*DIN*HD + n*DIN + k] = h1;
    }
}

// ===========================================================================
// Prep 2: X 2-way bf16 split (streaming).  g_xsp[z][s][m][k]
// ===========================================================================
__global__ __launch_bounds__(256) void split_x(
    const float* __restrict__ Xq, const float* __restrict__ Xk, const float* __restrict__ Xv)
{
    const int z = blockIdx.y;
    const float* X = (z == 0) ? Xq : (z == 1) ? Xk : Xv;
    const int idx = blockIdx.x * 256 + threadIdx.x;        // float4 index
    float4 v = ((const float4*)X)[idx];
    uint16_t a0[4], a1[4];
    split2(v.x, a0[0], a1[0]);
    split2(v.y, a0[1], a1[1]);
    split2(v.z, a0[2], a1[2]);
    split2(v.w, a0[3], a1[3]);
    uint2* out = (uint2*)g_xsp;
    const int NX4 = BATCH*LEN*DIN/4;
    out[(z*2 + 0)*NX4 + idx] = make_uint2((uint32_t)a0[0] | ((uint32_t)a0[1]<<16),
                                          (uint32_t)a0[2] | ((uint32_t)a0[3]<<16));
    out[(z*2 + 1)*NX4 + idx] = make_uint2((uint32_t)a1[0] | ((uint32_t)a1[1]<<16),
                                          (uint32_t)a1[2] | ((uint32_t)a1[3]<<16));
}

// ===========================================================================
// Projection GEMM via mma.sync bf16, 3 cross terms (i+j<=1).
// Tile 128x128, 256 threads; smem A0,A1,B0,B1 x 16KB = 64KB.
// occupancy 2 (NOT 3 — 84-reg cap spills the 64-reg accumulator file).
// Epilogue writes split2 bf16 planes (Q scaled 1/8).
// ===========================================================================
#define PSM_BYTES (4*16384)

__global__ __launch_bounds__(256, 2) void proj_mma_kernel()
{
    extern __shared__ __align__(16) char sm[];   // [A0 A1 B0 B1] x 16KB

    const int tid = threadIdx.x;
    const int z   = blockIdx.z;
    const int n0  = blockIdx.x * 128;
    const int m0  = blockIdx.y * 128;

    const uint16_t* xsp = g_xsp + z * (2*BATCH*LEN*DIN);
    const uint16_t* wsp = g_wsp + z * (2*DIN*HD);
    uint32_t* gdst = (z == 0) ? g_qs : (z == 1) ? g_ks : g_vs;
    const float sc = (z == 0) ? 0.125f : 1.0f;

    const int w      = tid >> 5;
    const int lane   = tid & 31;
    const int warp_m = (w & 3) * 32;
    const int warp_n = (w >> 2) * 64;

    const int rA = lane & 15;
    const int hA = lane >> 4;
    const int rB = (lane & 7) | ((lane >> 4) << 3);
    const int hB = (lane >> 3) & 1;
    const uint32_t smb = smem_u32(sm);

    float acc[2][8][4];
    #pragma unroll
    for (int mf = 0; mf < 2; ++mf)
        #pragma unroll
        for (int nf = 0; nf < 8; ++nf)
            #pragma unroll
            for (int e = 0; e < 4; ++e) acc[mf][nf][e] = 0.0f;

    for (int c = 0; c < 8; ++c) {
        const int c64 = c * 64;
        __syncthreads();

        // --- copy pre-split X chunk [128 m][64 k] x2 -> smA (swizzled) ---
        #pragma unroll
        for (int i = 0; i < 8; ++i) {
            const int u   = tid + i*256;      // 0..2047 16B chunks
            const int s   = u >> 10;
            const int rem = u & 1023;
            const int r   = rem >> 3;
            const int c16 = rem & 7;
            const uint4 v = *(const uint4*)(xsp + s*(BATCH*LEN*DIN) + (m0 + r)*DIN + c64 + c16*8);
            const uint32_t off = (uint32_t)(s*16384 + r*128 + ((c16 ^ (r & 7)) << 4));
            *(uint4*)(sm + off) = v;
        }
        // --- copy pre-split W chunk [128 n][64 k] x2 -> smB (swizzled) ---
        #pragma unroll
        for (int i = 0; i < 8; ++i) {
            const int u   = tid + i*256;
            const int s   = u >> 10;
            const int rem = u & 1023;
            const int r   = rem >> 3;
            const int c16 = rem & 7;
            const uint4 v = *(const uint4*)(wsp + s*(DIN*HD) + (n0 + r)*DIN + c64 + c16*8);
            const uint32_t off = (uint32_t)(32768 + s*16384 + r*128 + ((c16 ^ (r & 7)) << 4));
            *(uint4*)(sm + off) = v;
        }
        __syncthreads();

        #pragma unroll
        for (int ks = 0; ks < 4; ++ks) {
            uint32_t a[2][2][4];
            #pragma unroll
            for (int s = 0; s < 2; ++s)
                #pragma unroll
                for (int mf = 0; mf < 2; ++mf) {
                    const uint32_t addr = smb + s*16384
                        + (uint32_t)((warp_m + mf*16 + rA)*128)
                        + (uint32_t)((((ks*2) + hA) ^ (rA & 7)) << 4);
                    ldsm_x4(a[s][mf], addr);
                }
            #pragma unroll
            for (int bj = 0; bj < 2; ++bj) {
                uint32_t bf[4][4];
                #pragma unroll
                for (int nf2 = 0; nf2 < 4; ++nf2) {
                    const uint32_t addr = smb + 32768 + bj*16384
                        + (uint32_t)((warp_n + nf2*16 + rB)*128)
                        + (uint32_t)((((ks*2) + hB) ^ (rB & 7)) << 4);
                    ldsm_x4(bf[nf2], addr);
                }
                #pragma unroll
                for (int ai = 0; ai < 2; ++ai) {
                    if (ai + bj > 1) break;   // terms (0,0),(0,1),(1,0)
                    #pragma unroll
                    for (int mf = 0; mf < 2; ++mf)
                        #pragma unroll
                        for (int nf = 0; nf < 8; ++nf)
                            mma_bf16(acc[mf][nf], a[ai][mf],
                                     bf[nf >> 1][(nf & 1)*2], bf[nf >> 1][(nf & 1)*2 + 1]);
                }
            }
        }
    }

    // --- epilogue: split2 -> bf16 planes [s][bh][l][d] ---
    const int g  = lane >> 2;
    const int tc = lane & 3;
    #pragma unroll
    for (int mf = 0; mf < 2; ++mf)
        #pragma unroll
        for (int nf = 0; nf < 8; ++nf) {
            const int mrow = m0 + warp_m + mf*16 + g;
            const int col  = n0 + warp_n + nf*8 + tc*2;
            const int b = mrow >> 10, l = mrow & 1023;
            const int h = col >> 6,   d = col & 63;
            const int bh = b*NHEAD + h;
            #pragma unroll
            for (int half = 0; half < 2; ++half) {
                const float x0 = acc[mf][nf][half*2 + 0] * sc;
                const float x1 = acc[mf][nf][half*2 + 1] * sc;
                const uint32_t lo = pack2(x0, x1);
                const uint32_t hi = pack2(x0 - bf16lo(x0), x1 - bf16lo(x1));
                const int row = l + half*8;
                const uint32_t idx = (uint32_t)((bh*1024 + row)*32 + (d >> 1));
                gdst[idx]             = lo;
                gdst[PLANE_U32 + idx] = hi;
            }
        }
}

// ===========================================================================
// Causal flash attention via mma.sync bf16 (pre-split planes).
// S = QK^T with 3 split products (drop q1*k1); PV with 3 products.
// ===========================================================================
#define ASM_BYTES (48*1024)

__global__ __launch_bounds__(128) void attn_mma_kernel(float* __restrict__ out)
{
    extern __shared__ __align__(16) char sm[];
    const uint32_t smb = smem_u32(sm);
    const uint32_t Kbase = smb + 16384;
    const uint32_t Vbase = smb + 32768;

    const int tid  = threadIdx.x;
    const int lane = tid & 31;
    const int w    = tid >> 5;
    const int bh   = blockIdx.x;                 // 0..63
    const int qt   = 15 - (int)blockIdx.y;       // heavy q-tiles first
    const int q0   = qt * 64;

    const uint16_t* qsp = (const uint16_t*)g_qs;
    const uint16_t* ksp = (const uint16_t*)g_ks;
    const uint16_t* vsp = (const uint16_t*)g_vs;
    const int PLANE_U16 = PLANE_U32 * 2;

    const int warp_m = w * 16;
    const int rA = lane & 15;
    const int hA = lane >> 4;
    const int rB = (lane & 7) | ((lane >> 4) << 3);
    const int hB = (lane >> 3) & 1;
    const int g  = lane >> 2;
    const int t4 = lane & 3;

    // ---- copy Q planes (64 rows x 128B x 2) ----
    #pragma unroll
    for (int i = 0; i < 8; ++i) {
        const int t   = tid + i*128;
        const int s   = t >> 9;
        const int rem = t & 511;
        const int r   = rem >> 3;
        const int c16 = rem & 7;
        const uint4 v = *(const uint4*)(qsp + s*PLANE_U16 + ((bh*1024 + q0 + r)*64) + c16*8);
        const uint32_t off = (uint32_t)(s*8192 + r*128 + ((c16 ^ (r & 7)) << 4));
        *(uint4*)(sm + off) = v;
    }
    __syncthreads();

    uint32_t qf[2][4][4];
    #pragma unroll
    for (int s = 0; s < 2; ++s)
        #pragma unroll
        for (int ks = 0; ks < 4; ++ks) {
            const uint32_t addr = smb + s*8192
                + (uint32_t)((warp_m + rA)*128)
                + (uint32_t)((((ks*2) + hA) ^ (rA & 7)) << 4);
            ldsm_x4(qf[s][ks], addr);
        }

    float O[8][4];
    #pragma unroll
    for (int nf = 0; nf < 8; ++nf)
        #pragma unroll
        for (int e = 0; e < 4; ++e) O[nf][e] = 0.0f;
    float m0 = -1e30f, m1 = -1e30f, l0 = 0.0f, l1 = 0.0f;

    for (int kt = 0; kt <= qt; ++kt) {
        const int k0 = kt * 64;
        __syncthreads();

        #pragma unroll
        for (int i = 0; i < 16; ++i) {
            const int t    = tid + i*128;
            const int tens = t >> 10;
            const int rem  = t & 1023;
            const int s    = rem >> 9;
            const int rem2 = rem & 511;
            const int r    = rem2 >> 3;
            const int c16  = rem2 & 7;
            const uint16_t* src = (tens == 0) ? ksp : vsp;
            const uint4 v = *(const uint4*)(src + s*PLANE_U16 + ((bh*1024 + k0 + r)*64) + c16*8);
            const uint32_t off = (uint32_t)(16384 + tens*16384 + s*8192 + r*128
                                            + ((c16 ^ (r & 7)) << 4));
            *(uint4*)(sm + off) = v;
        }
        __syncthreads();

        float c[8][4];
        #pragma unroll
        for (int nf = 0; nf < 8; ++nf)
            #pragma unroll
            for (int e = 0; e < 4; ++e) c[nf][e] = 0.0f;

        #pragma unroll
        for (int ks = 0; ks < 4; ++ks) {
            uint32_t kb[2][4][4];
            #pragma unroll
            for (int s = 0; s < 2; ++s)
                #pragma unroll
                for (int nf2 = 0; nf2 < 4; ++nf2) {
                    const uint32_t addr = Kbase + s*8192
                        + (uint32_t)((nf2*16 + rB)*128)
                        + (uint32_t)((((ks*2) + hB) ^ (rB & 7)) << 4);
                    ldsm_x4(kb[s][nf2], addr);
                }
            #pragma unroll
            for (int sq = 0; sq < 2; ++sq)
                #pragma unroll
                for (int sk = 0; sk < 2; ++sk) {
                    if (sq + sk > 1) continue;   // drop q1*k1 residual product
                    #pragma unroll
                    for (int nf = 0; nf < 8; ++nf)
                        mma_bf16(c[nf], qf[sq][ks],
                                 kb[sk][nf >> 1][(nf & 1)*2], kb[sk][nf >> 1][(nf & 1)*2 + 1]);
                }
        }

        if (kt == qt) {
            #pragma unroll
            for (int nf = 0; nf < 8; ++nf) {
                const int col = nf*8 + t4*2;
                const int r0  = warp_m + g;
                const int r1  = r0 + 8;
                if (col     > r0) c[nf][0] = -1e30f;
                if (col + 1 > r0) c[nf][1] = -1e30f;
                if (col     > r1) c[nf][2] = -1e30f;
                if (col + 1 > r1) c[nf][3] = -1e30f;
            }
        }

        float mx0 = -1e30f, mx1 = -1e30f;
        #pragma unroll
        for (int nf = 0; nf < 8; ++nf) {
            mx0 = fmaxf(mx0, fmaxf(c[nf][0], c[nf][1]));
            mx1 = fmaxf(mx1, fmaxf(c[nf][2], c[nf][3]));
        }
        mx0 = fmaxf(mx0, __shfl_xor_sync(0xffffffffu, mx0, 1));
        mx0 = fmaxf(mx0, __shfl_xor_sync(0xffffffffu, mx0, 2));
        mx1 = fmaxf(mx1, __shfl_xor_sync(0xffffffffu, mx1, 1));
        mx1 = fmaxf(mx1, __shfl_xor_sync(0xffffffffu, mx1, 2));

        const float mn0 = fmaxf(m0, mx0);
        const float mn1 = fmaxf(m1, mx1);
        const float corr0 = __expf(m0 - mn0);
        const float corr1 = __expf(m1 - mn1);
        m0 = mn0; m1 = mn1;

        float s0 = 0.0f, s1 = 0.0f;
        #pragma unroll
        for (int nf = 0; nf < 8; ++nf) {
            c[nf][0] = __expf(c[nf][0] - mn0); s0 += c[nf][0];
            c[nf][1] = __expf(c[nf][1] - mn0); s0 += c[nf][1];
            c[nf][2] = __expf(c[nf][2] - mn1); s1 += c[nf][2];
            c[nf][3] = __expf(c[nf][3] - mn1); s1 += c[nf][3];
        }
        s0 += __shfl_xor_sync(0xffffffffu, s0, 1);
        s0 += __shfl_xor_sync(0xffffffffu, s0, 2);
        s1 += __shfl_xor_sync(0xffffffffu, s1, 1);
        s1 += __shfl_xor_sync(0xffffffffu, s1, 2);
        l0 = l0*corr0 + s0;
        l1 = l1*corr1 + s1;

        #pragma unroll
        for (int nf = 0; nf < 8; ++nf) {
            O[nf][0] *= corr0; O[nf][1] *= corr0;
            O[nf][2] *= corr1; O[nf][3] *= corr1;
        }

        #pragma unroll
        for (int ks2 = 0; ks2 < 4; ++ks2) {
            const float va = c[2*ks2][0],   vb_ = c[2*ks2][1],
                        vc = c[2*ks2][2],   vd = c[2*ks2][3];
            const float wa = c[2*ks2+1][0], wb = c[2*ks2+1][1],
                        wc = c[2*ks2+1][2], wd = c[2*ks2+1][3];
            uint32_t pa0[4], pa1[4];
            pa0[0] = pack2(va, vb_); pa0[1] = pack2(vc, vd);
            pa0[2] = pack2(wa, wb);  pa0[3] = pack2(wc, wd);
            pa1[0] = pack2(va - bf16lo(va), vb_ - bf16lo(vb_));
            pa1[1] = pack2(vc - bf16lo(vc), vd - bf16lo(vd));
            pa1[2] = pack2(wa - bf16lo(wa), wb - bf16lo(wb));
            pa1[3] = pack2(wc - bf16lo(wc), wd - bf16lo(wd));

            uint32_t vbf[2][4][4];
            const int keyrow = ks2*16 + (lane & 15);
            #pragma unroll
            for (int s = 0; s < 2; ++s)
                #pragma unroll
                for (int dp = 0; dp < 4; ++dp) {
                    const uint32_t addr = Vbase + s*8192
                        + (uint32_t)(keyrow*128)
                        + (uint32_t)(((dp*2 + (lane >> 4)) ^ (keyrow & 7)) << 4);
                    ldsm_x4_t(vbf[s][dp], addr);
                }
            #pragma unroll
            for (int nf = 0; nf < 8; ++nf) {
                const uint32_t b00 = vbf[0][nf >> 1][(nf & 1)*2];
                const uint32_t b01 = vbf[0][nf >> 1][(nf & 1)*2 + 1];
                const uint32_t b10 = vbf[1][nf >> 1][(nf & 1)*2];
                const uint32_t b11 = vbf[1][nf >> 1][(nf & 1)*2 + 1];
                mma_bf16(O[nf], pa0, b00, b01);
                mma_bf16(O[nf], pa1, b00, b01);
                mma_bf16(O[nf], pa0, b10, b11);
            }
        }
    }

    const float inv0 = 1.0f / l0;
    const float inv1 = 1.0f / l1;
    const int b = bh >> 3;
    const int h = bh & 7;
    const int row0 = q0 + warp_m + g;
    const int row1 = row0 + 8;
    #pragma unroll
    for (int nf = 0; nf < 8; ++nf) {
        const int d = nf*8 + t4*2;
        *(float2*)(out + (b*LEN + row0)*HD + h*HDIM + d) =
            make_float2(O[nf][0]*inv0, O[nf][1]*inv0);
        *(float2*)(out + (b*LEN + row1)*HD + h*HDIM + d) =
            make_float2(O[nf][2]*inv1, O[nf][3]*inv1);
    }
}

// ---------------------------------------------------------------------------
extern "C" void kernel_launch(void* const* d_in, const int* in_sizes, int n_in,
                              void* d_out, int out_size)
{
    (void)in_sizes; (void)n_in; (void)out_size;
    const float* Qseq = (const float*)d_in[0];
    const float* Kseq = (const float*)d_in[1];
    const float* Vseq = (const float*)d_in[2];
    const float* WQ   = (const float*)d_in[3];
    const float* WK   = (const float*)d_in[4];
    const float* WV   = (const float*)d_in[5];
    float* out = (float*)d_out;

    transpose_split_w<<<dim3(16,16,3), 256>>>(WQ, WK, WV);
    split_x<<<dim3(BATCH*LEN*DIN/4/256, 3), 256>>>(Qseq, Kseq, Vseq);

    cudaFuncSetAttribute(proj_mma_kernel, cudaFuncAttributeMaxDynamicSharedMemorySize, PSM_BYTES);
    proj_mma_kernel<<<dim3(4, 64, 3), 256, PSM_BYTES>>>();

    cudaFuncSetAttribute(attn_mma_kernel, cudaFuncAttributeMaxDynamicSharedMemorySize, ASM_BYTES);
    attn_mma_kernel<<<dim3(64, 16), 128, ASM_BYTES>>>(out);
}